// round 9
// baseline (speedup 1.0000x reference)
#include <cuda_runtime.h>
#include <math.h>
#include <stdint.h>

// Problem constants
#define B_    128
#define F_    1024
#define D_IN  128
#define H1_   512
#define H2_   512
#define E_    256
#define H_    256
#define NSH   5
#define MROWS (B_ * F_)   // 131072

// ---------------- scratch (device globals; no allocation allowed) ----------
__device__ int8_t g_sq1[(size_t)MROWS * D_IN];
__device__ int8_t g_sq2[(size_t)MROWS * D_IN];
__device__ float  g_h1[(size_t)MROWS * H1_];
__device__ int8_t g_h1q1[(size_t)MROWS * H1_];
__device__ int8_t g_h1q2[(size_t)MROWS * H1_];
__device__ float  g_h2[(size_t)MROWS * H2_];
__device__ int8_t g_h2q1[(size_t)MROWS * H2_];
__device__ int8_t g_h2q2[(size_t)MROWS * H2_];
__device__ int8_t g_w1q1[H1_ * D_IN], g_w1q2[H1_ * D_IN];
__device__ int8_t g_w2q1[H2_ * H1_],  g_w2q2[H2_ * H1_];
__device__ int8_t g_w3q1[E_ * H2_],   g_w3q2[E_ * H2_];
__device__ float  g_dsa0[MROWS], g_dsa1[MROWS], g_dsa2[MROWS];
__device__ float  g_dsw1[H1_], g_dsw2[H2_], g_dsw3[E_];
__device__ float  g_emb[(size_t)MROWS * E_];   // 134 MB

// ===================== low-level helpers ===================================
__device__ __forceinline__ uint32_t smem_u32(const void* p) {
    uint32_t a;
    asm("{ .reg .u64 t; cvta.to.shared.u64 t, %1; cvt.u32.u64 %0, t; }"
        : "=r"(a) : "l"(p));
    return a;
}

__device__ __forceinline__ void cp_async16(uint32_t dst, const void* src) {
    asm volatile("cp.async.cg.shared.global [%0], [%1], 16;\n"
                 :: "r"(dst), "l"(src));
}
#define CP_COMMIT() asm volatile("cp.async.commit_group;\n" ::: "memory")
#define CP_WAIT1()  asm volatile("cp.async.wait_group 1;\n" ::: "memory")
#define CP_WAIT0()  asm volatile("cp.async.wait_group 0;\n" ::: "memory")

__device__ __forceinline__ void ldsm4(uint32_t* r, uint32_t addr) {
    asm volatile("ldmatrix.sync.aligned.m8n8.x4.shared.b16 {%0,%1,%2,%3}, [%4];\n"
                 : "=r"(r[0]), "=r"(r[1]), "=r"(r[2]), "=r"(r[3]) : "r"(addr));
}

// int8 IMMA: m16n8k32, int32 accumulate. Fragment byte layout is identical to
// the bf16 m16n8k16 case, so the same ldmatrix addressing applies.
__device__ __forceinline__ void mma_s8(int* d, const uint32_t* a, const uint32_t* b) {
    asm volatile(
        "mma.sync.aligned.m16n8k32.row.col.s32.s8.s8.s32 "
        "{%0,%1,%2,%3}, {%4,%5,%6,%7}, {%8,%9}, {%0,%1,%2,%3};\n"
        : "+r"(d[0]), "+r"(d[1]), "+r"(d[2]), "+r"(d[3])
        : "r"(a[0]), "r"(a[1]), "r"(a[2]), "r"(a[3]), "r"(b[0]), "r"(b[1]));
}

// ============ row quantization: x ~= (srow/127) * (Q1 + Q2/254) ============
// One warp per row. Reads the row once, computes rowmax, emits both digits
// and the dequant scale ds = srow/127.  K = NI*128.
template <int NI>
__global__ __launch_bounds__(256) void quant_rows_kernel(
    const float* __restrict__ src, int rows,
    int8_t* __restrict__ q1, int8_t* __restrict__ q2, float* __restrict__ ds)
{
    const int K = NI * 128;
    const int w = blockIdx.x * 8 + (threadIdx.x >> 5);
    if (w >= rows) return;
    const int lane = threadIdx.x & 31;
    const float4* s4 = reinterpret_cast<const float4*>(src + (size_t)w * K);

    float4 v[NI];
    float mx = 0.f;
#pragma unroll
    for (int i = 0; i < NI; i++) {
        v[i] = s4[lane + 32 * i];
        mx = fmaxf(mx, fmaxf(fmaxf(fabsf(v[i].x), fabsf(v[i].y)),
                             fmaxf(fabsf(v[i].z), fabsf(v[i].w))));
    }
#pragma unroll
    for (int o = 16; o; o >>= 1) mx = fmaxf(mx, __shfl_xor_sync(0xffffffffu, mx, o));
    const float srow = fmaxf(mx, 1e-20f);
    const float qs = 127.f / srow;
    if (lane == 0) ds[w] = srow * (1.f / 127.f);

    int* o1 = reinterpret_cast<int*>(q1 + (size_t)w * K);
    int* o2 = reinterpret_cast<int*>(q2 + (size_t)w * K);
#pragma unroll
    for (int i = 0; i < NI; i++) {
        const float x0 = v[i].x * qs, x1 = v[i].y * qs, x2 = v[i].z * qs, x3 = v[i].w * qs;
        const float h0 = rintf(x0), h1 = rintf(x1), h2 = rintf(x2), h3 = rintf(x3);
        const int a0 = (int)h0, a1 = (int)h1, a2 = (int)h2, a3 = (int)h3;
        const int b0 = (int)rintf((x0 - h0) * 254.f);
        const int b1 = (int)rintf((x1 - h1) * 254.f);
        const int b2 = (int)rintf((x2 - h2) * 254.f);
        const int b3 = (int)rintf((x3 - h3) * 254.f);
        o1[lane + 32 * i] = (a0 & 255) | ((a1 & 255) << 8) | ((a2 & 255) << 16) | (a3 << 24);
        o2[lane + 32 * i] = (b0 & 255) | ((b1 & 255) << 8) | ((b2 & 255) << 16) | (b3 << 24);
    }
}

// =================== int8 IMMA GEMM: C = act(deq(A @ W^T) + bias) ==========
// A digits [M,K] int8, W digits [N,K] int8, per-row dequant scales dsa/dsw.
// D = dsa[m]*dsw[n]*(P0 + P12/254),  P0 = A1W1, P12 = A1W2 + A2W1 (one acc).
// CTA tile 128x128, 512 threads, warp grid 4x4, warp tile 32x32.
// BK=128 int8 (128B rows), XOR swizzle, 2-stage cp.async.
static constexpr int TQ      = 128 * 128;          // 16384 B per digit tile
static constexpr int STAGE_B = 4 * TQ;             // A1|A2|W1|W2 = 65536 B
static constexpr int GEMM_SM = 2 * STAGE_B;        // 131072 B

template <int ACT>
__global__ __launch_bounds__(512, 1) void gemm_i8_kernel(
    int M, int N, int K,
    const int8_t* __restrict__ A1q, const int8_t* __restrict__ A2q,
    const int8_t* __restrict__ W1q, const int8_t* __restrict__ W2q,
    const float* __restrict__ dsa, const float* __restrict__ dsw,
    const float* __restrict__ bias,
    float* __restrict__ C)
{
    extern __shared__ char smem[];
    const uint32_t sbase = smem_u32(smem);
    const int tid  = threadIdx.x;
    const int lane = tid & 31;
    const int wid  = tid >> 5;            // 0..15
    const int m0 = blockIdx.y * 128;
    const int n0 = blockIdx.x * 128;
    const int wm = (wid & 3) * 32;        // warp m-offset (4 warps in m)
    const int wn = (wid >> 2) * 32;       // warp n-offset (4 warps in n)

    int accP[2][4][4], accQ[2][4][4];
#pragma unroll
    for (int i = 0; i < 2; i++)
#pragma unroll
        for (int j = 0; j < 4; j++)
#pragma unroll
            for (int k = 0; k < 4; k++) { accP[i][j][k] = 0; accQ[i][j][k] = 0; }

    // ---- cp.async geometry: 8 x 16B per thread per stage ----
    // chunk id = i*512+tid; t = i>>1 (A1|A2|W1|W2); rb = (i&1)*64 + tid/8; c16 = tid&7
    const int rb0 = tid >> 3;
    const int c0  = tid & 7;
    const int64_t kk64 = (int64_t)64 * K;
    const int8_t* gbase[4];
    gbase[0] = A1q + (size_t)(m0 + rb0) * K + c0 * 16;
    gbase[1] = A2q + (size_t)(m0 + rb0) * K + c0 * 16;
    gbase[2] = W1q + (size_t)(n0 + rb0) * K + c0 * 16;
    gbase[3] = W2q + (size_t)(n0 + rb0) * K + c0 * 16;
    const uint32_t sd0 = sbase + rb0 * 128 + (((uint32_t)(c0 ^ (rb0 & 7))) << 4);

    // ---- ldmatrix row bases ----
    uint32_t aRow[2], aX[2];
#pragma unroll
    for (int ma = 0; ma < 2; ma++) {
        const int r = wm + ma * 16 + (lane & 15);
        aRow[ma] = (uint32_t)(r * 128);
        aX[ma]   = (uint32_t)(r & 7);
    }
    uint32_t bRow[2], bX[2];
#pragma unroll
    for (int pb = 0; pb < 2; pb++) {
        const int r = wn + pb * 16 + (lane & 7) + ((lane >> 1) & 8);
        bRow[pb] = (uint32_t)(r * 128);
        bX[pb]   = (uint32_t)(r & 7);
    }
    const uint32_t ac0 = (uint32_t)(lane >> 4);
    const uint32_t bc0 = (uint32_t)((lane >> 3) & 1);

    const int NC = K >> 7;   // chunks of 128 int8

    auto prefetch = [&](int cc, int st) {
        const uint32_t so = sd0 + (uint32_t)(st * STAGE_B);
        const int kk = cc * 128;
#pragma unroll
        for (int i = 0; i < 8; i++) {
            const int t = i >> 1;
            cp_async16(so + t * TQ + (i & 1) * 8192,
                       gbase[t] + kk + (i & 1) * kk64);
        }
        CP_COMMIT();
    };

    prefetch(0, 0);

    for (int cc = 0; cc < NC; cc++) {
        if (cc + 1 < NC) { prefetch(cc + 1, (cc + 1) & 1); CP_WAIT1(); }
        else             { CP_WAIT0(); }
        __syncthreads();

        const uint32_t st = sbase + (cc & 1) * STAGE_B;
#pragma unroll
        for (int s = 0; s < 4; s++) {
            const uint32_t ac = ac0 + 2 * s;
            const uint32_t bc = bc0 + 2 * s;

            // a1 (A digit 1), b1 (W digit 1), b2 (W digit 2)
            uint32_t a1[2][4];
#pragma unroll
            for (int ma = 0; ma < 2; ma++)
                ldsm4(a1[ma], st + aRow[ma] + ((ac ^ aX[ma]) << 4));
            uint32_t b1[4][2], b2[4][2];
#pragma unroll
            for (int pb = 0; pb < 2; pb++) {
                uint32_t r[4];
                ldsm4(r, st + 2 * TQ + bRow[pb] + ((bc ^ bX[pb]) << 4));
                b1[2 * pb][0] = r[0]; b1[2 * pb][1] = r[1];
                b1[2 * pb + 1][0] = r[2]; b1[2 * pb + 1][1] = r[3];
            }
#pragma unroll
            for (int pb = 0; pb < 2; pb++) {
                uint32_t r[4];
                ldsm4(r, st + 3 * TQ + bRow[pb] + ((bc ^ bX[pb]) << 4));
                b2[2 * pb][0] = r[0]; b2[2 * pb][1] = r[1];
                b2[2 * pb + 1][0] = r[2]; b2[2 * pb + 1][1] = r[3];
            }

            // P0 += A1*W1
#pragma unroll
            for (int ma = 0; ma < 2; ma++)
#pragma unroll
                for (int na = 0; na < 4; na++) mma_s8(accP[ma][na], a1[ma], b1[na]);

            // a2 loads complete under the next MMA group
            uint32_t a2[2][4];
#pragma unroll
            for (int ma = 0; ma < 2; ma++)
                ldsm4(a2[ma], st + TQ + aRow[ma] + ((ac ^ aX[ma]) << 4));

            // P12 += A1*W2
#pragma unroll
            for (int ma = 0; ma < 2; ma++)
#pragma unroll
                for (int na = 0; na < 4; na++) mma_s8(accQ[ma][na], a1[ma], b2[na]);

            // P12 += A2*W1
#pragma unroll
            for (int ma = 0; ma < 2; ma++)
#pragma unroll
                for (int na = 0; na < 4; na++) mma_s8(accQ[ma][na], a2[ma], b1[na]);
        }
        __syncthreads();
    }

    // epilogue: dequant + bias (+ReLU), fp32 stores
    const float inv254 = 1.f / 254.f;
#pragma unroll
    for (int ma = 0; ma < 2; ma++) {
        const int r0 = m0 + wm + ma * 16 + (lane >> 2);
        const int r1 = r0 + 8;
        const float sA0 = __ldg(&dsa[r0]);
        const float sA1 = __ldg(&dsa[r1]);
#pragma unroll
        for (int na = 0; na < 4; na++) {
            const int col = n0 + wn + na * 8 + ((lane & 3) << 1);
            const float sw0 = __ldg(&dsw[col]);
            const float sw1 = __ldg(&dsw[col + 1]);
            const float bz0 = __ldg(&bias[col]);
            const float bz1 = __ldg(&bias[col + 1]);
            float v00 = sA0 * sw0 * ((float)accP[ma][na][0] + (float)accQ[ma][na][0] * inv254) + bz0;
            float v01 = sA0 * sw1 * ((float)accP[ma][na][1] + (float)accQ[ma][na][1] * inv254) + bz1;
            float v10 = sA1 * sw0 * ((float)accP[ma][na][2] + (float)accQ[ma][na][2] * inv254) + bz0;
            float v11 = sA1 * sw1 * ((float)accP[ma][na][3] + (float)accQ[ma][na][3] * inv254) + bz1;
            if (ACT) {
                v00 = fmaxf(v00, 0.f); v01 = fmaxf(v01, 0.f);
                v10 = fmaxf(v10, 0.f); v11 = fmaxf(v11, 0.f);
            }
            *reinterpret_cast<float2*>(&C[(size_t)r0 * N + col]) = make_float2(v00, v01);
            *reinterpret_cast<float2*>(&C[(size_t)r1 * N + col]) = make_float2(v10, v11);
        }
    }
}

// ============ fused shuffle: 5 x (online-softmax attention + LSTM) =========
// One block per batch, 1024 threads (32 warps). Single emb pass per iteration:
// warp w streams f-rows [w*32, w*32+32), maintaining flash-style (m, l, acc).
__global__ __launch_bounds__(1024) void shuffle_kernel(
    const float* __restrict__ emb, const int* __restrict__ length,
    const float* __restrict__ W_ih, const float* __restrict__ W_hh,
    const float* __restrict__ b_ih, const float* __restrict__ b_hh,
    float* __restrict__ out)
{
    const int b    = blockIdx.x;
    const int tid  = threadIdx.x;
    const int warp = tid >> 5, lane = tid & 31;

    __shared__ __align__(16) float s_q[H_];         // qt
    __shared__ __align__(16) float s_c[H_];         // ct
    __shared__ __align__(16) float s_x[E_];         // attended
    __shared__ __align__(16) float s_g[4 * H_];     // lstm gates
    __shared__ __align__(16) float s_part[32][E_ + 4];
    __shared__ float s_m[32], s_l[32], s_fac[32];
    __shared__ float s_invL;

    if (tid < H_) { s_q[tid] = 0.f; s_c[tid] = 0.f; }
    __syncthreads();

    const int len = length[b];
    const float* eb = emb + (size_t)b * F_ * E_;
    const float4* q4 = reinterpret_cast<const float4*>(s_q);
    const float4* x4 = reinterpret_cast<const float4*>(s_x);

    for (int it = 0; it < NSH; it++) {
        // ---- single-pass attention: logits + online softmax + attended ----
        float m = -INFINITY, l = 0.f;
        float4 a0 = make_float4(0.f, 0.f, 0.f, 0.f);
        float4 a1 = make_float4(0.f, 0.f, 0.f, 0.f);
        const float4 qv0 = q4[lane], qv1 = q4[lane + 32];
        const int fb = warp * 32;
#pragma unroll 2
        for (int ff = 0; ff < 32; ff++) {
            const int f = fb + ff;
            const float4* r4 = reinterpret_cast<const float4*>(eb + (size_t)f * E_);
            const float4 v0 = r4[lane], v1 = r4[lane + 32];
            float d = v0.x * qv0.x + v0.y * qv0.y + v0.z * qv0.z + v0.w * qv0.w;
            d = fmaf(v1.x, qv1.x, d); d = fmaf(v1.y, qv1.y, d);
            d = fmaf(v1.z, qv1.z, d); d = fmaf(v1.w, qv1.w, d);
#pragma unroll
            for (int o = 16; o; o >>= 1) d += __shfl_xor_sync(0xffffffffu, d, o);
            if (f < len) {
                const float mn = fmaxf(m, d);
                const float sc = expf(m - mn);    // 0 on first valid row
                const float p  = expf(d - mn);
                l = l * sc + p;
                a0.x = fmaf(a0.x, sc, p * v0.x); a0.y = fmaf(a0.y, sc, p * v0.y);
                a0.z = fmaf(a0.z, sc, p * v0.z); a0.w = fmaf(a0.w, sc, p * v0.w);
                a1.x = fmaf(a1.x, sc, p * v1.x); a1.y = fmaf(a1.y, sc, p * v1.y);
                a1.z = fmaf(a1.z, sc, p * v1.z); a1.w = fmaf(a1.w, sc, p * v1.w);
                m = mn;
            }
        }
        {
            float4* sp = reinterpret_cast<float4*>(s_part[warp]);
            sp[lane] = a0;
            sp[lane + 32] = a1;
            if (lane == 0) { s_m[warp] = m; s_l[warp] = l; }
        }
        __syncthreads();

        // ---- combine 32 warp-partials (warp 0) ----
        if (tid < 32) {
            const float mw = s_m[tid];
            float M = mw;
#pragma unroll
            for (int o = 16; o; o >>= 1) M = fmaxf(M, __shfl_xor_sync(0xffffffffu, M, o));
            const float fac = expf(mw - M);       // 0 if warp saw no valid rows
            s_fac[tid] = fac;
            float L = s_l[tid] * fac;
#pragma unroll
            for (int o = 16; o; o >>= 1) L += __shfl_xor_sync(0xffffffffu, L, o);
            if (tid == 0) s_invL = 1.f / L;
        }
        __syncthreads();

        if (tid < E_) {
            float s = 0.f;
#pragma unroll
            for (int w = 0; w < 32; w++) s = fmaf(s_part[w][tid], s_fac[w], s);
            s_x[tid] = s * s_invL;
        }
        __syncthreads();

        // ---- LSTM gates: warp per 32 rows ----
        {
            const float4 xv0 = x4[lane], xv1 = x4[lane + 32];
            const float4 qv0b = q4[lane], qv1b = q4[lane + 32];
            for (int j = warp * 32, je = j + 32; j < je; j++) {
                const float4* wi4 = reinterpret_cast<const float4*>(W_ih + (size_t)j * E_);
                const float4* wh4 = reinterpret_cast<const float4*>(W_hh + (size_t)j * H_);
                const float4 w0 = wi4[lane], w1 = wi4[lane + 32];
                const float4 h0 = wh4[lane], h1 = wh4[lane + 32];
                float d = w0.x * xv0.x + w0.y * xv0.y + w0.z * xv0.z + w0.w * xv0.w;
                d = fmaf(w1.x, xv1.x, d); d = fmaf(w1.y, xv1.y, d);
                d = fmaf(w1.z, xv1.z, d); d = fmaf(w1.w, xv1.w, d);
                d = fmaf(h0.x, qv0b.x, d); d = fmaf(h0.y, qv0b.y, d);
                d = fmaf(h0.z, qv0b.z, d); d = fmaf(h0.w, qv0b.w, d);
                d = fmaf(h1.x, qv1b.x, d); d = fmaf(h1.y, qv1b.y, d);
                d = fmaf(h1.z, qv1b.z, d); d = fmaf(h1.w, qv1b.w, d);
#pragma unroll
                for (int o = 16; o; o >>= 1) d += __shfl_xor_sync(0xffffffffu, d, o);
                if (lane == 0) s_g[j] = d + b_ih[j] + b_hh[j];
            }
        }
        __syncthreads();

        // ---- state update (gate order i, f, g, o) ----
        if (tid < H_) {
            const float gi = 1.f / (1.f + expf(-s_g[tid]));
            const float gf = 1.f / (1.f + expf(-s_g[H_ + tid]));
            const float gg = tanhf(s_g[2 * H_ + tid]);
            const float go = 1.f / (1.f + expf(-s_g[3 * H_ + tid]));
            const float c = gf * s_c[tid] + gi * gg;
            s_c[tid] = c;
            s_q[tid] = go * tanhf(c);
        }
        __syncthreads();
    }

    // ---- output: concat(attended, qt) ----
    if (tid < E_ + H_)
        out[b * (E_ + H_) + tid] = (tid < E_) ? s_x[tid] : s_q[tid - E_];
}

// ---------------- launch ----------------------------------------------------
extern "C" void kernel_launch(void* const* d_in, const int* in_sizes, int n_in,
                              void* d_out, int out_size)
{
    const float* state = (const float*)d_in[0];
    const int*   length= (const int*)  d_in[1];
    const float* W1    = (const float*)d_in[2];
    const float* b1    = (const float*)d_in[3];
    const float* W2    = (const float*)d_in[4];
    const float* b2    = (const float*)d_in[5];
    const float* W3    = (const float*)d_in[6];
    const float* b3    = (const float*)d_in[7];
    const float* W_ih  = (const float*)d_in[8];
    const float* W_hh  = (const float*)d_in[9];
    const float* b_ih  = (const float*)d_in[10];
    const float* b_hh  = (const float*)d_in[11];
    float* out = (float*)d_out;

    int8_t *sq1, *sq2, *h1q1, *h1q2, *h2q1, *h2q2;
    int8_t *w1q1, *w1q2, *w2q1, *w2q2, *w3q1, *w3q2;
    float *h1, *h2, *emb, *dsa0, *dsa1, *dsa2, *dsw1, *dsw2, *dsw3;
    cudaGetSymbolAddress((void**)&sq1,  g_sq1);
    cudaGetSymbolAddress((void**)&sq2,  g_sq2);
    cudaGetSymbolAddress((void**)&h1,   g_h1);
    cudaGetSymbolAddress((void**)&h1q1, g_h1q1);
    cudaGetSymbolAddress((void**)&h1q2, g_h1q2);
    cudaGetSymbolAddress((void**)&h2,   g_h2);
    cudaGetSymbolAddress((void**)&h2q1, g_h2q1);
    cudaGetSymbolAddress((void**)&h2q2, g_h2q2);
    cudaGetSymbolAddress((void**)&w1q1, g_w1q1);
    cudaGetSymbolAddress((void**)&w1q2, g_w1q2);
    cudaGetSymbolAddress((void**)&w2q1, g_w2q1);
    cudaGetSymbolAddress((void**)&w2q2, g_w2q2);
    cudaGetSymbolAddress((void**)&w3q1, g_w3q1);
    cudaGetSymbolAddress((void**)&w3q2, g_w3q2);
    cudaGetSymbolAddress((void**)&dsa0, g_dsa0);
    cudaGetSymbolAddress((void**)&dsa1, g_dsa1);
    cudaGetSymbolAddress((void**)&dsa2, g_dsa2);
    cudaGetSymbolAddress((void**)&dsw1, g_dsw1);
    cudaGetSymbolAddress((void**)&dsw2, g_dsw2);
    cudaGetSymbolAddress((void**)&dsw3, g_dsw3);
    cudaGetSymbolAddress((void**)&emb,  g_emb);

    cudaFuncSetAttribute(gemm_i8_kernel<1>,
                         cudaFuncAttributeMaxDynamicSharedMemorySize, GEMM_SM);
    cudaFuncSetAttribute(gemm_i8_kernel<0>,
                         cudaFuncAttributeMaxDynamicSharedMemorySize, GEMM_SM);

    // quantize inputs and weights (warp per row)
    quant_rows_kernel<1><<<MROWS / 8, 256>>>(state, MROWS, sq1, sq2, dsa0);
    quant_rows_kernel<1><<<H1_ / 8, 256>>>(W1, H1_, w1q1, w1q2, dsw1);
    quant_rows_kernel<4><<<H2_ / 8, 256>>>(W2, H2_, w2q1, w2q2, dsw2);
    quant_rows_kernel<4><<<E_ / 8, 256>>>(W3, E_, w3q1, w3q2, dsw3);

    // embedder MLP on int8 IMMA tensor cores
    {
        dim3 g1(H1_ / 128, MROWS / 128);
        gemm_i8_kernel<1><<<g1, 512, GEMM_SM>>>(
            MROWS, H1_, D_IN, sq1, sq2, w1q1, w1q2, dsa0, dsw1, b1, h1);
        quant_rows_kernel<4><<<MROWS / 8, 256>>>(h1, MROWS, h1q1, h1q2, dsa1);

        dim3 g2(H2_ / 128, MROWS / 128);
        gemm_i8_kernel<1><<<g2, 512, GEMM_SM>>>(
            MROWS, H2_, H1_, h1q1, h1q2, w2q1, w2q2, dsa1, dsw2, b2, h2);
        quant_rows_kernel<4><<<MROWS / 8, 256>>>(h2, MROWS, h2q1, h2q2, dsa2);

        dim3 g3(E_ / 128, MROWS / 128);
        gemm_i8_kernel<0><<<g3, 512, GEMM_SM>>>(
            MROWS, E_, H2_, h2q1, h2q2, w3q1, w3q2, dsa2, dsw3, b3, emb);
    }

    // fused shuffle loop (online-softmax attention + LSTM x5) + output
    shuffle_kernel<<<B_, 1024>>>(emb, length, W_ih, W_hh, b_ih, b_hh, out);
}

// round 10
// speedup vs baseline: 3.2208x; 3.2208x over previous
#include <cuda_runtime.h>
#include <cuda_fp16.h>
#include <math.h>
#include <stdint.h>

// Problem constants
#define B_    128
#define F_    1024
#define D_IN  128
#define H1_   512
#define H2_   512
#define E_    256
#define H_    256
#define NSH   5
#define MROWS (B_ * F_)   // 131072

// ---------------- scratch (device globals; no allocation allowed) ----------
__device__ __half g_sth[(size_t)MROWS * D_IN];
__device__ __half g_h1[(size_t)MROWS * H1_];
__device__ __half g_h2[(size_t)MROWS * H2_];
__device__ __half g_w1[H1_ * D_IN];
__device__ __half g_w2[H2_ * H1_];
__device__ __half g_w3[E_ * H2_];
__device__ float  g_emb[(size_t)MROWS * E_];   // 134 MB

// ===================== low-level helpers ===================================
__device__ __forceinline__ uint32_t smem_u32(const void* p) {
    uint32_t a;
    asm("{ .reg .u64 t; cvta.to.shared.u64 t, %1; cvt.u32.u64 %0, t; }"
        : "=r"(a) : "l"(p));
    return a;
}

__device__ __forceinline__ void cp_async16(uint32_t dst, const void* src) {
    asm volatile("cp.async.cg.shared.global [%0], [%1], 16;\n"
                 :: "r"(dst), "l"(src));
}
#define CP_COMMIT() asm volatile("cp.async.commit_group;\n" ::: "memory")
#define CP_WAIT2()  asm volatile("cp.async.wait_group 2;\n" ::: "memory")
#define CP_WAIT1()  asm volatile("cp.async.wait_group 1;\n" ::: "memory")
#define CP_WAIT0()  asm volatile("cp.async.wait_group 0;\n" ::: "memory")

__device__ __forceinline__ void ldsm4(uint32_t* r, uint32_t addr) {
    asm volatile("ldmatrix.sync.aligned.m8n8.x4.shared.b16 {%0,%1,%2,%3}, [%4];\n"
                 : "=r"(r[0]), "=r"(r[1]), "=r"(r[2]), "=r"(r[3]) : "r"(addr));
}

// fp16 HMMA m16n8k16, fp32 accumulate
__device__ __forceinline__ void mma_f16(float* d, const uint32_t* a, const uint32_t* b) {
    asm volatile(
        "mma.sync.aligned.m16n8k16.row.col.f32.f16.f16.f32 "
        "{%0,%1,%2,%3}, {%4,%5,%6,%7}, {%8,%9}, {%0,%1,%2,%3};\n"
        : "+f"(d[0]), "+f"(d[1]), "+f"(d[2]), "+f"(d[3])
        : "r"(a[0]), "r"(a[1]), "r"(a[2]), "r"(a[3]), "r"(b[0]), "r"(b[1]));
}

__device__ __forceinline__ uint32_t pack_h2(float a, float b) {
    __half2 t = __floats2half2_rn(a, b);
    return reinterpret_cast<uint32_t&>(t);
}

// =================== fp16 HMMA GEMM: C = act(A @ W^T + bias) ================
// A [M,K] fp16 row-major, W [N,K] fp16 row-major. Single pass, fp32 acc.
// CTA tile 128x256, 512 threads, warp grid 2m x 8n, warp tile 64x32.
// BK=64 (128B rows, XOR swizzle), 3-stage cp.async pipeline, 1 CTA/SM.
static constexpr int TA      = 128 * 128;          // 16384 B  A tile
static constexpr int TW      = 256 * 128;          // 32768 B  W tile
static constexpr int OFF_A   = 0;
static constexpr int OFF_W   = TA;
static constexpr int STAGE_B = TA + TW;            // 49152 B
static constexpr int GEMM_SM = 3 * STAGE_B;        // 147456 B

template <int ACT, int OUT_HALF>
__global__ __launch_bounds__(512, 1) void gemm_f16_kernel(
    int M, int N, int K,
    const __half* __restrict__ A, const __half* __restrict__ W,
    const float* __restrict__ bias,
    float* __restrict__ C, __half* __restrict__ Ch)
{
    extern __shared__ char smem[];
    const uint32_t sbase = smem_u32(smem);
    const int tid  = threadIdx.x;
    const int lane = tid & 31;
    const int wid  = tid >> 5;            // 0..15
    const int m0 = blockIdx.y * 128;
    const int n0 = blockIdx.x * 256;
    const int wm = (wid & 1) * 64;        // warp m-offset
    const int wn = (wid >> 1) * 32;       // warp n-offset

    float acc[4][4][4];
#pragma unroll
    for (int i = 0; i < 4; i++)
#pragma unroll
        for (int j = 0; j < 4; j++)
#pragma unroll
            for (int k = 0; k < 4; k++) acc[i][j][k] = 0.f;

    // ---- cp.async geometry: 6 x 16B per thread per stage ----
    // chunk id = i*512 + tid; row = id>>3 (0..383), c16 = id&7.
    // rows 0-127: A tile | 128-383: W tile
    const __half* gsrc[6];
    uint32_t sdst[6];
#pragma unroll
    for (int i = 0; i < 6; i++) {
        const int row = i * 64 + (tid >> 3);
        const int c16 = tid & 7;
        const int isW = (row >= 128);
        const int rb  = isW ? (row - 128) : row;
        const __half* bp = isW ? W : A;
        const int grow = (isW ? n0 : m0) + rb;
        gsrc[i] = bp + (size_t)grow * K + c16 * 8;
        sdst[i] = sbase + (isW ? OFF_W : OFF_A) + rb * 128
                + (((uint32_t)(c16 ^ (rb & 7))) << 4);
    }

    // ---- ldmatrix row bases ----
    uint32_t aRow[4], aX[4];
#pragma unroll
    for (int am = 0; am < 4; am++) {
        const int r = wm + am * 16 + (lane & 15);
        aRow[am] = (uint32_t)(r * 128);
        aX[am]   = (uint32_t)(r & 7);
    }
    uint32_t bRow[2], bX[2];
#pragma unroll
    for (int pb = 0; pb < 2; pb++) {
        const int r = wn + pb * 16 + (lane & 7) + ((lane >> 1) & 8);
        bRow[pb] = (uint32_t)(r * 128);
        bX[pb]   = (uint32_t)(r & 7);
    }
    const uint32_t ac0 = (uint32_t)(lane >> 4);
    const uint32_t bc0 = (uint32_t)((lane >> 3) & 1);

    const int NC = K >> 6;   // chunks of 64 fp16

    auto prefetch = [&](int cc, int st) {
        const uint32_t so = (uint32_t)(st * STAGE_B);
        const int kk = cc * 64;
#pragma unroll
        for (int i = 0; i < 6; i++) cp_async16(sdst[i] + so, gsrc[i] + kk);
        CP_COMMIT();
    };

    prefetch(0, 0);
    if (NC > 1) prefetch(1, 1);

    int st_c = 0;   // stage of current chunk
    for (int cc = 0; cc < NC; cc++) {
        if (cc + 2 < NC) {
            int st2 = st_c + 2; if (st2 >= 3) st2 -= 3;
            prefetch(cc + 2, st2);
            CP_WAIT2();
        } else if (cc + 1 < NC) {
            CP_WAIT1();
        } else {
            CP_WAIT0();
        }
        __syncthreads();

        const uint32_t st = sbase + st_c * STAGE_B;
#pragma unroll
        for (int s = 0; s < 4; s++) {
            const uint32_t ac = ac0 + 2 * s;
            const uint32_t bc = bc0 + 2 * s;

            uint32_t ah[4][4];
#pragma unroll
            for (int am = 0; am < 4; am++)
                ldsm4(ah[am], st + OFF_A + aRow[am] + ((ac ^ aX[am]) << 4));
            uint32_t bv[4][2];
#pragma unroll
            for (int pb = 0; pb < 2; pb++) {
                uint32_t r[4];
                ldsm4(r, st + OFF_W + bRow[pb] + ((bc ^ bX[pb]) << 4));
                bv[2 * pb][0] = r[0]; bv[2 * pb][1] = r[1];
                bv[2 * pb + 1][0] = r[2]; bv[2 * pb + 1][1] = r[3];
            }
#pragma unroll
            for (int am = 0; am < 4; am++)
#pragma unroll
                for (int an = 0; an < 4; an++) mma_f16(acc[am][an], ah[am], bv[an]);
        }
        __syncthreads();
        if (++st_c == 3) st_c = 0;
    }

    // epilogue: bias (+ReLU), store fp32 or fp16
#pragma unroll
    for (int am = 0; am < 4; am++) {
        const int r0 = m0 + wm + am * 16 + (lane >> 2);
        const int r1 = r0 + 8;
#pragma unroll
        for (int an = 0; an < 4; an++) {
            const int col = n0 + wn + an * 8 + ((lane & 3) << 1);
            const float bz0 = __ldg(&bias[col]);
            const float bz1 = __ldg(&bias[col + 1]);
            float v00 = acc[am][an][0] + bz0;
            float v01 = acc[am][an][1] + bz1;
            float v10 = acc[am][an][2] + bz0;
            float v11 = acc[am][an][3] + bz1;
            if (ACT) {
                v00 = fmaxf(v00, 0.f); v01 = fmaxf(v01, 0.f);
                v10 = fmaxf(v10, 0.f); v11 = fmaxf(v11, 0.f);
            }
            if (OUT_HALF) {
                *reinterpret_cast<uint32_t*>(&Ch[(size_t)r0 * N + col]) = pack_h2(v00, v01);
                *reinterpret_cast<uint32_t*>(&Ch[(size_t)r1 * N + col]) = pack_h2(v10, v11);
            } else {
                *reinterpret_cast<float2*>(&C[(size_t)r0 * N + col]) = make_float2(v00, v01);
                *reinterpret_cast<float2*>(&C[(size_t)r1 * N + col]) = make_float2(v10, v11);
            }
        }
    }
}

// ---------------- fp32 -> fp16 converts ------------------------------------
__device__ __forceinline__ void conv4(const float* src, __half* dst, int i) {
    float4 v = *reinterpret_cast<const float4*>(src + i);
    *reinterpret_cast<uint2*>(&dst[i]) =
        make_uint2(pack_h2(v.x, v.y), pack_h2(v.z, v.w));
}

__global__ __launch_bounds__(256) void conv_weights_kernel(
    const float* __restrict__ W1, __half* __restrict__ w1,
    const float* __restrict__ W2, __half* __restrict__ w2,
    const float* __restrict__ W3, __half* __restrict__ w3)
{
    const int N1 = H1_ * D_IN, N2 = H2_ * H1_, N3 = E_ * H2_;
    int i = (blockIdx.x * 256 + threadIdx.x) * 4;
    if (i < N1)                conv4(W1, w1, i);
    else if (i < N1 + N2)      conv4(W2, w2, i - N1);
    else if (i < N1 + N2 + N3) conv4(W3, w3, i - N1 - N2);
}

__global__ __launch_bounds__(256) void conv_state_kernel(
    const float* __restrict__ src, __half* __restrict__ dst)
{
    int i = (blockIdx.x * 256 + threadIdx.x) * 4;
    conv4(src, dst, i);
}

// ============ fused shuffle: 5 x (online-softmax attention + LSTM) =========
// One block per batch, 1024 threads (32 warps). Single emb pass per iteration:
// warp w streams f-rows [w*32, w*32+32), maintaining flash-style (m, l, acc).
__global__ __launch_bounds__(1024) void shuffle_kernel(
    const float* __restrict__ emb, const int* __restrict__ length,
    const float* __restrict__ W_ih, const float* __restrict__ W_hh,
    const float* __restrict__ b_ih, const float* __restrict__ b_hh,
    float* __restrict__ out)
{
    const int b    = blockIdx.x;
    const int tid  = threadIdx.x;
    const int warp = tid >> 5, lane = tid & 31;

    __shared__ __align__(16) float s_q[H_];         // qt
    __shared__ __align__(16) float s_c[H_];         // ct
    __shared__ __align__(16) float s_x[E_];         // attended
    __shared__ __align__(16) float s_g[4 * H_];     // lstm gates
    __shared__ __align__(16) float s_part[32][E_ + 4];
    __shared__ float s_m[32], s_l[32], s_fac[32];
    __shared__ float s_invL;

    if (tid < H_) { s_q[tid] = 0.f; s_c[tid] = 0.f; }
    __syncthreads();

    const int len = length[b];
    const float* eb = emb + (size_t)b * F_ * E_;
    const float4* q4 = reinterpret_cast<const float4*>(s_q);
    const float4* x4 = reinterpret_cast<const float4*>(s_x);

    for (int it = 0; it < NSH; it++) {
        // ---- single-pass attention: logits + online softmax + attended ----
        float m = -INFINITY, l = 0.f;
        float4 a0 = make_float4(0.f, 0.f, 0.f, 0.f);
        float4 a1 = make_float4(0.f, 0.f, 0.f, 0.f);
        const float4 qv0 = q4[lane], qv1 = q4[lane + 32];
        const int fb = warp * 32;
#pragma unroll 2
        for (int ff = 0; ff < 32; ff++) {
            const int f = fb + ff;
            const float4* r4 = reinterpret_cast<const float4*>(eb + (size_t)f * E_);
            const float4 v0 = r4[lane], v1 = r4[lane + 32];
            float d = v0.x * qv0.x + v0.y * qv0.y + v0.z * qv0.z + v0.w * qv0.w;
            d = fmaf(v1.x, qv1.x, d); d = fmaf(v1.y, qv1.y, d);
            d = fmaf(v1.z, qv1.z, d); d = fmaf(v1.w, qv1.w, d);
#pragma unroll
            for (int o = 16; o; o >>= 1) d += __shfl_xor_sync(0xffffffffu, d, o);
            if (f < len) {
                const float mn = fmaxf(m, d);
                const float sc = expf(m - mn);    // 0 on first valid row
                const float p  = expf(d - mn);
                l = l * sc + p;
                a0.x = fmaf(a0.x, sc, p * v0.x); a0.y = fmaf(a0.y, sc, p * v0.y);
                a0.z = fmaf(a0.z, sc, p * v0.z); a0.w = fmaf(a0.w, sc, p * v0.w);
                a1.x = fmaf(a1.x, sc, p * v1.x); a1.y = fmaf(a1.y, sc, p * v1.y);
                a1.z = fmaf(a1.z, sc, p * v1.z); a1.w = fmaf(a1.w, sc, p * v1.w);
                m = mn;
            }
        }
        {
            float4* sp = reinterpret_cast<float4*>(s_part[warp]);
            sp[lane] = a0;
            sp[lane + 32] = a1;
            if (lane == 0) { s_m[warp] = m; s_l[warp] = l; }
        }
        __syncthreads();

        // ---- combine 32 warp-partials (warp 0) ----
        if (tid < 32) {
            const float mw = s_m[tid];
            float M = mw;
#pragma unroll
            for (int o = 16; o; o >>= 1) M = fmaxf(M, __shfl_xor_sync(0xffffffffu, M, o));
            const float fac = expf(mw - M);       // 0 if warp saw no valid rows
            s_fac[tid] = fac;
            float L = s_l[tid] * fac;
#pragma unroll
            for (int o = 16; o; o >>= 1) L += __shfl_xor_sync(0xffffffffu, L, o);
            if (tid == 0) s_invL = 1.f / L;
        }
        __syncthreads();

        if (tid < E_) {
            float s = 0.f;
#pragma unroll
            for (int w = 0; w < 32; w++) s = fmaf(s_part[w][tid], s_fac[w], s);
            s_x[tid] = s * s_invL;
        }
        __syncthreads();

        // ---- LSTM gates: warp per 32 rows ----
        {
            const float4 xv0 = x4[lane], xv1 = x4[lane + 32];
            const float4 qv0b = q4[lane], qv1b = q4[lane + 32];
            for (int j = warp * 32, je = j + 32; j < je; j++) {
                const float4* wi4 = reinterpret_cast<const float4*>(W_ih + (size_t)j * E_);
                const float4* wh4 = reinterpret_cast<const float4*>(W_hh + (size_t)j * H_);
                const float4 w0 = wi4[lane], w1 = wi4[lane + 32];
                const float4 h0 = wh4[lane], h1 = wh4[lane + 32];
                float d = w0.x * xv0.x + w0.y * xv0.y + w0.z * xv0.z + w0.w * xv0.w;
                d = fmaf(w1.x, xv1.x, d); d = fmaf(w1.y, xv1.y, d);
                d = fmaf(w1.z, xv1.z, d); d = fmaf(w1.w, xv1.w, d);
                d = fmaf(h0.x, qv0b.x, d); d = fmaf(h0.y, qv0b.y, d);
                d = fmaf(h0.z, qv0b.z, d); d = fmaf(h0.w, qv0b.w, d);
                d = fmaf(h1.x, qv1b.x, d); d = fmaf(h1.y, qv1b.y, d);
                d = fmaf(h1.z, qv1b.z, d); d = fmaf(h1.w, qv1b.w, d);
#pragma unroll
                for (int o = 16; o; o >>= 1) d += __shfl_xor_sync(0xffffffffu, d, o);
                if (lane == 0) s_g[j] = d + b_ih[j] + b_hh[j];
            }
        }
        __syncthreads();

        // ---- state update (gate order i, f, g, o) ----
        if (tid < H_) {
            const float gi = 1.f / (1.f + expf(-s_g[tid]));
            const float gf = 1.f / (1.f + expf(-s_g[H_ + tid]));
            const float gg = tanhf(s_g[2 * H_ + tid]);
            const float go = 1.f / (1.f + expf(-s_g[3 * H_ + tid]));
            const float c = gf * s_c[tid] + gi * gg;
            s_c[tid] = c;
            s_q[tid] = go * tanhf(c);
        }
        __syncthreads();
    }

    // ---- output: concat(attended, qt) ----
    if (tid < E_ + H_)
        out[b * (E_ + H_) + tid] = (tid < E_) ? s_x[tid] : s_q[tid - E_];
}

// ---------------- launch ----------------------------------------------------
extern "C" void kernel_launch(void* const* d_in, const int* in_sizes, int n_in,
                              void* d_out, int out_size)
{
    const float* state = (const float*)d_in[0];
    const int*   length= (const int*)  d_in[1];
    const float* W1    = (const float*)d_in[2];
    const float* b1    = (const float*)d_in[3];
    const float* W2    = (const float*)d_in[4];
    const float* b2    = (const float*)d_in[5];
    const float* W3    = (const float*)d_in[6];
    const float* b3    = (const float*)d_in[7];
    const float* W_ih  = (const float*)d_in[8];
    const float* W_hh  = (const float*)d_in[9];
    const float* b_ih  = (const float*)d_in[10];
    const float* b_hh  = (const float*)d_in[11];
    float* out = (float*)d_out;

    __half *sth, *h1, *h2, *w1, *w2, *w3;
    float *emb;
    cudaGetSymbolAddress((void**)&sth, g_sth);
    cudaGetSymbolAddress((void**)&h1,  g_h1);
    cudaGetSymbolAddress((void**)&h2,  g_h2);
    cudaGetSymbolAddress((void**)&w1,  g_w1);
    cudaGetSymbolAddress((void**)&w2,  g_w2);
    cudaGetSymbolAddress((void**)&w3,  g_w3);
    cudaGetSymbolAddress((void**)&emb, g_emb);

    cudaFuncSetAttribute(gemm_f16_kernel<1, 1>,
                         cudaFuncAttributeMaxDynamicSharedMemorySize, GEMM_SM);
    cudaFuncSetAttribute(gemm_f16_kernel<0, 0>,
                         cudaFuncAttributeMaxDynamicSharedMemorySize, GEMM_SM);

    // 1: weight converts
    {
        int n = H1_ * D_IN + H2_ * H1_ + E_ * H2_;
        conv_weights_kernel<<<n / 1024, 256>>>(W1, w1, W2, w2, W3, w3);
    }
    // 2: state convert
    conv_state_kernel<<<(MROWS * D_IN) / 1024, 256>>>(state, sth);

    // 3-5: embedder MLP, single-pass fp16 HMMA
    {
        dim3 g1(H1_ / 256, MROWS / 128);
        gemm_f16_kernel<1, 1><<<g1, 512, GEMM_SM>>>(
            MROWS, H1_, D_IN, sth, w1, b1, nullptr, h1);
        dim3 g2(H2_ / 256, MROWS / 128);
        gemm_f16_kernel<1, 1><<<g2, 512, GEMM_SM>>>(
            MROWS, H2_, H1_, h1, w2, b2, nullptr, h2);
        dim3 g3(E_ / 256, MROWS / 128);
        gemm_f16_kernel<0, 0><<<g3, 512, GEMM_SM>>>(
            MROWS, E_, H2_, h2, w3, b3, emb, nullptr);
    }

    // 6: fused shuffle loop (online-softmax attention + LSTM x5) + output
    shuffle_kernel<<<B_, 1024>>>(emb, length, W_ih, W_hh, b_ih, b_hh, out);
}

// round 11
// speedup vs baseline: 5.0910x; 1.5807x over previous
#include <cuda_runtime.h>
#include <cuda_fp16.h>
#include <math.h>
#include <stdint.h>

// Problem constants
#define B_    128
#define F_    1024
#define D_IN  128
#define H1_   512
#define H2_   512
#define E_    256
#define H_    256
#define NSH   5
#define MROWS (B_ * F_)   // 131072

// ---------------- scratch (device globals; no allocation allowed) ----------
__device__ __half g_sth[(size_t)MROWS * D_IN];
__device__ __half g_h1[(size_t)MROWS * H1_];
__device__ __half g_h2[(size_t)MROWS * H2_];
__device__ __half g_w1[H1_ * D_IN];
__device__ __half g_w2[H2_ * H1_];
__device__ __half g_w3[E_ * H2_];
__device__ __half g_embh[(size_t)MROWS * E_];   // 67 MB, fp16 emb

// ===================== low-level helpers ===================================
__device__ __forceinline__ uint32_t smem_u32(const void* p) {
    uint32_t a;
    asm("{ .reg .u64 t; cvta.to.shared.u64 t, %1; cvt.u32.u64 %0, t; }"
        : "=r"(a) : "l"(p));
    return a;
}

__device__ __forceinline__ void cp_async16(uint32_t dst, const void* src) {
    asm volatile("cp.async.cg.shared.global [%0], [%1], 16;\n"
                 :: "r"(dst), "l"(src));
}
#define CP_COMMIT() asm volatile("cp.async.commit_group;\n" ::: "memory")
#define CP_WAIT1()  asm volatile("cp.async.wait_group 1;\n" ::: "memory")
#define CP_WAIT0()  asm volatile("cp.async.wait_group 0;\n" ::: "memory")

__device__ __forceinline__ void ldsm4(uint32_t* r, uint32_t addr) {
    asm volatile("ldmatrix.sync.aligned.m8n8.x4.shared.b16 {%0,%1,%2,%3}, [%4];\n"
                 : "=r"(r[0]), "=r"(r[1]), "=r"(r[2]), "=r"(r[3]) : "r"(addr));
}

// fp16 HMMA m16n8k16, fp32 accumulate
__device__ __forceinline__ void mma_f16(float* d, const uint32_t* a, const uint32_t* b) {
    asm volatile(
        "mma.sync.aligned.m16n8k16.row.col.f32.f16.f16.f32 "
        "{%0,%1,%2,%3}, {%4,%5,%6,%7}, {%8,%9}, {%0,%1,%2,%3};\n"
        : "+f"(d[0]), "+f"(d[1]), "+f"(d[2]), "+f"(d[3])
        : "r"(a[0]), "r"(a[1]), "r"(a[2]), "r"(a[3]), "r"(b[0]), "r"(b[1]));
}

__device__ __forceinline__ uint32_t pack_h2(float a, float b) {
    __half2 t = __floats2half2_rn(a, b);
    return reinterpret_cast<uint32_t&>(t);
}

// =================== fp16 HMMA GEMM: C = act(A @ W^T + bias) ================
// A [M,K] fp16 row-major, W [N,K] fp16 row-major. Single pass, fp32 acc.
// CTA tile 128x256, 512 threads, warp grid 2m x 8n, warp tile 64x32.
// BK=128 (256B rows, XOR swizzle), 2-stage cp.async, 1 CTA/SM.
static constexpr int TA      = 128 * 256;          // 32768 B  A tile
static constexpr int TW      = 256 * 256;          // 65536 B  W tile
static constexpr int OFF_A   = 0;
static constexpr int OFF_W   = TA;
static constexpr int STAGE_B = TA + TW;            // 98304 B
static constexpr int GEMM_SM = 2 * STAGE_B;        // 196608 B

template <int ACT, int OUT_HALF>
__global__ __launch_bounds__(512, 1) void gemm_f16_kernel(
    int M, int N, int K,
    const __half* __restrict__ A, const __half* __restrict__ W,
    const float* __restrict__ bias,
    float* __restrict__ C, __half* __restrict__ Ch)
{
    extern __shared__ char smem[];
    const uint32_t sbase = smem_u32(smem);
    const int tid  = threadIdx.x;
    const int lane = tid & 31;
    const int wid  = tid >> 5;            // 0..15
    const int m0 = blockIdx.y * 128;
    const int n0 = blockIdx.x * 256;
    const int wm = (wid & 1) * 64;        // warp m-offset
    const int wn = (wid >> 1) * 32;       // warp n-offset

    float acc[4][4][4];
#pragma unroll
    for (int i = 0; i < 4; i++)
#pragma unroll
        for (int j = 0; j < 4; j++)
#pragma unroll
            for (int k = 0; k < 4; k++) acc[i][j][k] = 0.f;

    // ---- cp.async geometry: 12 x 16B per thread per stage ----
    // i<4: A tile (2048 chunks), i>=4: W tile (4096 chunks).
    // id -> row = id>>4, c16 = id&15 (16 chunks per 256B row).
    const __half* gsrc[12];
    uint32_t sdst[12];
#pragma unroll
    for (int i = 0; i < 12; i++) {
        const int isW = (i >= 4);
        const int id  = (isW ? (i - 4) : i) * 512 + tid;
        const int row = id >> 4;
        const int c16 = id & 15;
        const __half* bp = isW ? W : A;
        const int grow = (isW ? n0 : m0) + row;
        gsrc[i] = bp + (size_t)grow * K + c16 * 8;
        sdst[i] = sbase + (isW ? OFF_W : OFF_A) + row * 256
                + (((uint32_t)(c16 ^ (row & 7))) << 4);
    }

    // ---- ldmatrix row bases ----
    uint32_t aRow[4], aX[4];
#pragma unroll
    for (int am = 0; am < 4; am++) {
        const int r = wm + am * 16 + (lane & 15);
        aRow[am] = (uint32_t)(r * 256);
        aX[am]   = (uint32_t)(r & 7);
    }
    uint32_t bRow[2], bX[2];
#pragma unroll
    for (int pb = 0; pb < 2; pb++) {
        const int r = wn + pb * 16 + (lane & 7) + ((lane >> 1) & 8);
        bRow[pb] = (uint32_t)(r * 256);
        bX[pb]   = (uint32_t)(r & 7);
    }
    const uint32_t ac0 = (uint32_t)(lane >> 4);
    const uint32_t bc0 = (uint32_t)((lane >> 3) & 1);

    const int NC = K >> 7;   // chunks of 128 fp16

    auto prefetch = [&](int cc, int st) {
        const uint32_t so = (uint32_t)(st * STAGE_B);
        const int kk = cc * 128;
#pragma unroll
        for (int i = 0; i < 12; i++) cp_async16(sdst[i] + so, gsrc[i] + kk);
        CP_COMMIT();
    };

    prefetch(0, 0);

    for (int cc = 0; cc < NC; cc++) {
        if (cc + 1 < NC) { prefetch(cc + 1, (cc + 1) & 1); CP_WAIT1(); }
        else             { CP_WAIT0(); }
        __syncthreads();

        const uint32_t st = sbase + (cc & 1) * STAGE_B;
#pragma unroll
        for (int s = 0; s < 8; s++) {
            const uint32_t ac = ac0 + 2 * s;
            const uint32_t bc = bc0 + 2 * s;

            uint32_t ah[4][4];
#pragma unroll
            for (int am = 0; am < 4; am++)
                ldsm4(ah[am], st + OFF_A + aRow[am] + ((ac ^ aX[am]) << 4));
            uint32_t bv[4][2];
#pragma unroll
            for (int pb = 0; pb < 2; pb++) {
                uint32_t r[4];
                ldsm4(r, st + OFF_W + bRow[pb] + ((bc ^ bX[pb]) << 4));
                bv[2 * pb][0] = r[0]; bv[2 * pb][1] = r[1];
                bv[2 * pb + 1][0] = r[2]; bv[2 * pb + 1][1] = r[3];
            }
#pragma unroll
            for (int am = 0; am < 4; am++)
#pragma unroll
                for (int an = 0; an < 4; an++) mma_f16(acc[am][an], ah[am], bv[an]);
        }
        __syncthreads();
    }

    // epilogue: bias (+ReLU), store fp32 or fp16
#pragma unroll
    for (int am = 0; am < 4; am++) {
        const int r0 = m0 + wm + am * 16 + (lane >> 2);
        const int r1 = r0 + 8;
#pragma unroll
        for (int an = 0; an < 4; an++) {
            const int col = n0 + wn + an * 8 + ((lane & 3) << 1);
            const float bz0 = __ldg(&bias[col]);
            const float bz1 = __ldg(&bias[col + 1]);
            float v00 = acc[am][an][0] + bz0;
            float v01 = acc[am][an][1] + bz1;
            float v10 = acc[am][an][2] + bz0;
            float v11 = acc[am][an][3] + bz1;
            if (ACT) {
                v00 = fmaxf(v00, 0.f); v01 = fmaxf(v01, 0.f);
                v10 = fmaxf(v10, 0.f); v11 = fmaxf(v11, 0.f);
            }
            if (OUT_HALF) {
                *reinterpret_cast<uint32_t*>(&Ch[(size_t)r0 * N + col]) = pack_h2(v00, v01);
                *reinterpret_cast<uint32_t*>(&Ch[(size_t)r1 * N + col]) = pack_h2(v10, v11);
            } else {
                *reinterpret_cast<float2*>(&C[(size_t)r0 * N + col]) = make_float2(v00, v01);
                *reinterpret_cast<float2*>(&C[(size_t)r1 * N + col]) = make_float2(v10, v11);
            }
        }
    }
}

// ---------------- fp32 -> fp16 converts ------------------------------------
__device__ __forceinline__ void conv4(const float* src, __half* dst, int i) {
    float4 v = *reinterpret_cast<const float4*>(src + i);
    *reinterpret_cast<uint2*>(&dst[i]) =
        make_uint2(pack_h2(v.x, v.y), pack_h2(v.z, v.w));
}

__global__ __launch_bounds__(256) void conv_weights_kernel(
    const float* __restrict__ W1, __half* __restrict__ w1,
    const float* __restrict__ W2, __half* __restrict__ w2,
    const float* __restrict__ W3, __half* __restrict__ w3)
{
    const int N1 = H1_ * D_IN, N2 = H2_ * H1_, N3 = E_ * H2_;
    int i = (blockIdx.x * 256 + threadIdx.x) * 4;
    if (i < N1)                conv4(W1, w1, i);
    else if (i < N1 + N2)      conv4(W2, w2, i - N1);
    else if (i < N1 + N2 + N3) conv4(W3, w3, i - N1 - N2);
}

__global__ __launch_bounds__(256) void conv_state_kernel(
    const float* __restrict__ src, __half* __restrict__ dst)
{
    int i = (blockIdx.x * 256 + threadIdx.x) * 4;
    conv4(src, dst, i);
}

// ============ fused shuffle: 5 x (online-softmax attention + LSTM) =========
// One block per batch, 1024 threads (32 warps). emb is fp16: each lane reads
// one uint4 (8 halves) per f-row, covering e = lane*8 .. lane*8+7.
__global__ __launch_bounds__(1024) void shuffle_kernel(
    const __half* __restrict__ emb, const int* __restrict__ length,
    const float* __restrict__ W_ih, const float* __restrict__ W_hh,
    const float* __restrict__ b_ih, const float* __restrict__ b_hh,
    float* __restrict__ out)
{
    const int b    = blockIdx.x;
    const int tid  = threadIdx.x;
    const int warp = tid >> 5, lane = tid & 31;

    __shared__ __align__(16) float s_q[H_];         // qt
    __shared__ __align__(16) float s_c[H_];         // ct
    __shared__ __align__(16) float s_x[E_];         // attended
    __shared__ __align__(16) float s_g[4 * H_];     // lstm gates
    __shared__ __align__(16) float s_part[32][E_ + 4];
    __shared__ float s_m[32], s_l[32], s_fac[32];
    __shared__ float s_invL;

    if (tid < H_) { s_q[tid] = 0.f; s_c[tid] = 0.f; }
    __syncthreads();

    const int len = length[b];
    const __half* eb = emb + (size_t)b * F_ * E_;
    const float4* q4 = reinterpret_cast<const float4*>(s_q);
    const float4* x4 = reinterpret_cast<const float4*>(s_x);

    for (int it = 0; it < NSH; it++) {
        // ---- single-pass attention: logits + online softmax + attended ----
        float m = -INFINITY, l = 0.f;
        float acc[8];
#pragma unroll
        for (int j = 0; j < 8; j++) acc[j] = 0.f;
        // q values for e = lane*8 .. lane*8+7
        const float4 qa = q4[lane * 2], qb = q4[lane * 2 + 1];
        const float qv[8] = { qa.x, qa.y, qa.z, qa.w, qb.x, qb.y, qb.z, qb.w };
        const int fb = warp * 32;
#pragma unroll 2
        for (int ff = 0; ff < 32; ff++) {
            const int f = fb + ff;
            const uint4 hv = reinterpret_cast<const uint4*>(eb + (size_t)f * E_)[lane];
            const __half2* hp = reinterpret_cast<const __half2*>(&hv);
            float v[8];
#pragma unroll
            for (int k = 0; k < 4; k++) {
                const float2 f2 = __half22float2(hp[k]);
                v[2 * k] = f2.x; v[2 * k + 1] = f2.y;
            }
            float d = v[0] * qv[0];
#pragma unroll
            for (int j = 1; j < 8; j++) d = fmaf(v[j], qv[j], d);
#pragma unroll
            for (int o = 16; o; o >>= 1) d += __shfl_xor_sync(0xffffffffu, d, o);
            if (f < len) {
                const float mn = fmaxf(m, d);
                const float sc = expf(m - mn);    // 0 on first valid row
                const float p  = expf(d - mn);
                l = l * sc + p;
#pragma unroll
                for (int j = 0; j < 8; j++) acc[j] = fmaf(acc[j], sc, p * v[j]);
                m = mn;
            }
        }
        {
            float4* sp = reinterpret_cast<float4*>(s_part[warp]);
            sp[lane * 2]     = make_float4(acc[0], acc[1], acc[2], acc[3]);
            sp[lane * 2 + 1] = make_float4(acc[4], acc[5], acc[6], acc[7]);
            if (lane == 0) { s_m[warp] = m; s_l[warp] = l; }
        }
        __syncthreads();

        // ---- combine 32 warp-partials (warp 0) ----
        if (tid < 32) {
            const float mw = s_m[tid];
            float M = mw;
#pragma unroll
            for (int o = 16; o; o >>= 1) M = fmaxf(M, __shfl_xor_sync(0xffffffffu, M, o));
            const float fac = expf(mw - M);       // 0 if warp saw no valid rows
            s_fac[tid] = fac;
            float L = s_l[tid] * fac;
#pragma unroll
            for (int o = 16; o; o >>= 1) L += __shfl_xor_sync(0xffffffffu, L, o);
            if (tid == 0) s_invL = 1.f / L;
        }
        __syncthreads();

        if (tid < E_) {
            float s = 0.f;
#pragma unroll
            for (int w = 0; w < 32; w++) s = fmaf(s_part[w][tid], s_fac[w], s);
            s_x[tid] = s * s_invL;
        }
        __syncthreads();

        // ---- LSTM gates: warp per 32 rows ----
        {
            const float4 xv0 = x4[lane], xv1 = x4[lane + 32];
            const float4 qv0b = q4[lane], qv1b = q4[lane + 32];
            for (int j = warp * 32, je = j + 32; j < je; j++) {
                const float4* wi4 = reinterpret_cast<const float4*>(W_ih + (size_t)j * E_);
                const float4* wh4 = reinterpret_cast<const float4*>(W_hh + (size_t)j * H_);
                const float4 w0 = wi4[lane], w1 = wi4[lane + 32];
                const float4 h0 = wh4[lane], h1 = wh4[lane + 32];
                float d = w0.x * xv0.x + w0.y * xv0.y + w0.z * xv0.z + w0.w * xv0.w;
                d = fmaf(w1.x, xv1.x, d); d = fmaf(w1.y, xv1.y, d);
                d = fmaf(w1.z, xv1.z, d); d = fmaf(w1.w, xv1.w, d);
                d = fmaf(h0.x, qv0b.x, d); d = fmaf(h0.y, qv0b.y, d);
                d = fmaf(h0.z, qv0b.z, d); d = fmaf(h0.w, qv0b.w, d);
                d = fmaf(h1.x, qv1b.x, d); d = fmaf(h1.y, qv1b.y, d);
                d = fmaf(h1.z, qv1b.z, d); d = fmaf(h1.w, qv1b.w, d);
#pragma unroll
                for (int o = 16; o; o >>= 1) d += __shfl_xor_sync(0xffffffffu, d, o);
                if (lane == 0) s_g[j] = d + b_ih[j] + b_hh[j];
            }
        }
        __syncthreads();

        // ---- state update (gate order i, f, g, o) ----
        if (tid < H_) {
            const float gi = 1.f / (1.f + expf(-s_g[tid]));
            const float gf = 1.f / (1.f + expf(-s_g[H_ + tid]));
            const float gg = tanhf(s_g[2 * H_ + tid]);
            const float go = 1.f / (1.f + expf(-s_g[3 * H_ + tid]));
            const float c = gf * s_c[tid] + gi * gg;
            s_c[tid] = c;
            s_q[tid] = go * tanhf(c);
        }
        __syncthreads();
    }

    // ---- output: concat(attended, qt) ----
    if (tid < E_ + H_)
        out[b * (E_ + H_) + tid] = (tid < E_) ? s_x[tid] : s_q[tid - E_];
}

// ---------------- launch ----------------------------------------------------
extern "C" void kernel_launch(void* const* d_in, const int* in_sizes, int n_in,
                              void* d_out, int out_size)
{
    const float* state = (const float*)d_in[0];
    const int*   length= (const int*)  d_in[1];
    const float* W1    = (const float*)d_in[2];
    const float* b1    = (const float*)d_in[3];
    const float* W2    = (const float*)d_in[4];
    const float* b2    = (const float*)d_in[5];
    const float* W3    = (const float*)d_in[6];
    const float* b3    = (const float*)d_in[7];
    const float* W_ih  = (const float*)d_in[8];
    const float* W_hh  = (const float*)d_in[9];
    const float* b_ih  = (const float*)d_in[10];
    const float* b_hh  = (const float*)d_in[11];
    float* out = (float*)d_out;

    __half *sth, *h1, *h2, *w1, *w2, *w3, *embh;
    cudaGetSymbolAddress((void**)&sth,  g_sth);
    cudaGetSymbolAddress((void**)&h1,   g_h1);
    cudaGetSymbolAddress((void**)&h2,   g_h2);
    cudaGetSymbolAddress((void**)&w1,   g_w1);
    cudaGetSymbolAddress((void**)&w2,   g_w2);
    cudaGetSymbolAddress((void**)&w3,   g_w3);
    cudaGetSymbolAddress((void**)&embh, g_embh);

    cudaFuncSetAttribute(gemm_f16_kernel<1, 1>,
                         cudaFuncAttributeMaxDynamicSharedMemorySize, GEMM_SM);
    cudaFuncSetAttribute(gemm_f16_kernel<0, 1>,
                         cudaFuncAttributeMaxDynamicSharedMemorySize, GEMM_SM);

    // 1: weight converts
    {
        int n = H1_ * D_IN + H2_ * H1_ + E_ * H2_;
        conv_weights_kernel<<<n / 1024, 256>>>(W1, w1, W2, w2, W3, w3);
    }
    // 2: state convert
    conv_state_kernel<<<(MROWS * D_IN) / 1024, 256>>>(state, sth);

    // 3-5: embedder MLP, single-pass fp16 HMMA (BK=128)
    {
        dim3 g1(H1_ / 256, MROWS / 128);
        gemm_f16_kernel<1, 1><<<g1, 512, GEMM_SM>>>(
            MROWS, H1_, D_IN, sth, w1, b1, nullptr, h1);
        dim3 g2(H2_ / 256, MROWS / 128);
        gemm_f16_kernel<1, 1><<<g2, 512, GEMM_SM>>>(
            MROWS, H2_, H1_, h1, w2, b2, nullptr, h2);
        dim3 g3(E_ / 256, MROWS / 128);
        gemm_f16_kernel<0, 1><<<g3, 512, GEMM_SM>>>(
            MROWS, E_, H2_, h2, w3, b3, nullptr, embh);
    }

    // 6: fused shuffle loop (online-softmax attention + LSTM x5) + output
    shuffle_kernel<<<B_, 1024>>>(embh, length, W_ih, W_hh, b_ih, b_hh, out);
}

// round 12
// speedup vs baseline: 5.3298x; 1.0469x over previous
#include <cuda_runtime.h>
#include <cuda_fp16.h>
#include <math.h>
#include <stdint.h>

// Problem constants
#define B_    128
#define F_    1024
#define D_IN  128
#define H1_   512
#define H2_   512
#define E_    256
#define H_    256
#define NSH   5
#define MROWS (B_ * F_)   // 131072

// ---------------- scratch (device globals; no allocation allowed) ----------
__device__ __half g_h1[(size_t)MROWS * H1_];
__device__ __half g_h2[(size_t)MROWS * H2_];
__device__ __half g_w1[H1_ * D_IN];
__device__ __half g_w2[H2_ * H1_];
__device__ __half g_w3[E_ * H2_];
__device__ __half g_wih[4 * H_ * E_];
__device__ __half g_whh[4 * H_ * H_];
__device__ __half g_embh[(size_t)MROWS * E_];   // 67 MB, fp16 emb

// ===================== low-level helpers ===================================
__device__ __forceinline__ uint32_t smem_u32(const void* p) {
    uint32_t a;
    asm("{ .reg .u64 t; cvta.to.shared.u64 t, %1; cvt.u32.u64 %0, t; }"
        : "=r"(a) : "l"(p));
    return a;
}

__device__ __forceinline__ void cp_async16(uint32_t dst, const void* src) {
    asm volatile("cp.async.cg.shared.global [%0], [%1], 16;\n"
                 :: "r"(dst), "l"(src));
}
#define CP_COMMIT() asm volatile("cp.async.commit_group;\n" ::: "memory")
#define CP_WAIT1()  asm volatile("cp.async.wait_group 1;\n" ::: "memory")
#define CP_WAIT0()  asm volatile("cp.async.wait_group 0;\n" ::: "memory")

__device__ __forceinline__ void ldsm4(uint32_t* r, uint32_t addr) {
    asm volatile("ldmatrix.sync.aligned.m8n8.x4.shared.b16 {%0,%1,%2,%3}, [%4];\n"
                 : "=r"(r[0]), "=r"(r[1]), "=r"(r[2]), "=r"(r[3]) : "r"(addr));
}

// fp16 HMMA m16n8k16, fp32 accumulate
__device__ __forceinline__ void mma_f16(float* d, const uint32_t* a, const uint32_t* b) {
    asm volatile(
        "mma.sync.aligned.m16n8k16.row.col.f32.f16.f16.f32 "
        "{%0,%1,%2,%3}, {%4,%5,%6,%7}, {%8,%9}, {%0,%1,%2,%3};\n"
        : "+f"(d[0]), "+f"(d[1]), "+f"(d[2]), "+f"(d[3])
        : "r"(a[0]), "r"(a[1]), "r"(a[2]), "r"(a[3]), "r"(b[0]), "r"(b[1]));
}

__device__ __forceinline__ uint32_t pack_h2(float a, float b) {
    __half2 t = __floats2half2_rn(a, b);
    return reinterpret_cast<uint32_t&>(t);
}

// =================== fp16 HMMA GEMM: C = act(A @ W^T + bias) ================
// CTA tile 128x256, 512 threads, warp grid 2m x 8n, warp tile 64x32.
// BK=128 (256B rows, XOR swizzle), 2-stage cp.async, 1 CTA/SM.
// CONV_A: A is fp32 in global; staged via LDG->cvt->STS (used for layer 1,
// where K=128 -> single chunk, latency is prologue-only).
static constexpr int TA      = 128 * 256;          // 32768 B  A tile
static constexpr int TW      = 256 * 256;          // 65536 B  W tile
static constexpr int OFF_A   = 0;
static constexpr int OFF_W   = TA;
static constexpr int STAGE_B = TA + TW;            // 98304 B
static constexpr int GEMM_SM = 2 * STAGE_B;        // 196608 B

template <int ACT, int OUT_HALF, int CONV_A>
__global__ __launch_bounds__(512, 1) void gemm_f16_kernel(
    int M, int N, int K,
    const __half* __restrict__ A, const float* __restrict__ Afp,
    const __half* __restrict__ W,
    const float* __restrict__ bias,
    float* __restrict__ C, __half* __restrict__ Ch)
{
    extern __shared__ char smem[];
    const uint32_t sbase = smem_u32(smem);
    const int tid  = threadIdx.x;
    const int lane = tid & 31;
    const int wid  = tid >> 5;            // 0..15
    const int m0 = blockIdx.y * 128;
    const int n0 = blockIdx.x * 256;
    const int wm = (wid & 1) * 64;        // warp m-offset
    const int wn = (wid >> 1) * 32;       // warp n-offset

    float acc[4][4][4];
#pragma unroll
    for (int i = 0; i < 4; i++)
#pragma unroll
        for (int j = 0; j < 4; j++)
#pragma unroll
            for (int k = 0; k < 4; k++) acc[i][j][k] = 0.f;

    // ---- staging geometry ----
    // W tile: 8 x 16B cp.async per thread. A tile: 4 x 16B (cp.async or LDG/STS).
    const __half* gW[8];
    uint32_t sW[8];
#pragma unroll
    for (int i = 0; i < 8; i++) {
        const int id  = i * 512 + tid;       // 0..4095
        const int row = id >> 4;
        const int c16 = id & 15;
        gW[i] = W + (size_t)(n0 + row) * K + c16 * 8;
        sW[i] = sbase + OFF_W + row * 256 + (((uint32_t)(c16 ^ (row & 7))) << 4);
    }
    const __half* gA[4];
    const float*  gAf[4];
    uint32_t sA[4];
#pragma unroll
    for (int i = 0; i < 4; i++) {
        const int id  = i * 512 + tid;       // 0..2047
        const int row = id >> 4;
        const int c16 = id & 15;
        if (CONV_A) gAf[i] = Afp + (size_t)(m0 + row) * K + c16 * 8;
        else        gA[i]  = A   + (size_t)(m0 + row) * K + c16 * 8;
        sA[i] = sbase + OFF_A + row * 256 + (((uint32_t)(c16 ^ (row & 7))) << 4);
    }

    // ---- ldmatrix row bases ----
    uint32_t aRow[4], aX[4];
#pragma unroll
    for (int am = 0; am < 4; am++) {
        const int r = wm + am * 16 + (lane & 15);
        aRow[am] = (uint32_t)(r * 256);
        aX[am]   = (uint32_t)(r & 7);
    }
    uint32_t bRow[2], bX[2];
#pragma unroll
    for (int pb = 0; pb < 2; pb++) {
        const int r = wn + pb * 16 + (lane & 7) + ((lane >> 1) & 8);
        bRow[pb] = (uint32_t)(r * 256);
        bX[pb]   = (uint32_t)(r & 7);
    }
    const uint32_t ac0 = (uint32_t)(lane >> 4);
    const uint32_t bc0 = (uint32_t)((lane >> 3) & 1);

    const int NC = K >> 7;   // chunks of 128 fp16

    auto prefetch = [&](int cc, int st) {
        const uint32_t so = (uint32_t)(st * STAGE_B);
        const int kk = cc * 128;
#pragma unroll
        for (int i = 0; i < 8; i++) cp_async16(sW[i] + so, gW[i] + kk);
        if (CONV_A) {
#pragma unroll
            for (int i = 0; i < 4; i++) {
                const float4 u = *reinterpret_cast<const float4*>(gAf[i] + kk);
                const float4 v = *reinterpret_cast<const float4*>(gAf[i] + kk + 4);
                uint4 pk;
                pk.x = pack_h2(u.x, u.y); pk.y = pack_h2(u.z, u.w);
                pk.z = pack_h2(v.x, v.y); pk.w = pack_h2(v.z, v.w);
                *reinterpret_cast<uint4*>(smem + (sA[i] + so - sbase)) = pk;
            }
        } else {
#pragma unroll
            for (int i = 0; i < 4; i++) cp_async16(sA[i] + so, gA[i] + kk);
        }
        CP_COMMIT();
    };

    prefetch(0, 0);

    for (int cc = 0; cc < NC; cc++) {
        if (cc + 1 < NC) { prefetch(cc + 1, (cc + 1) & 1); CP_WAIT1(); }
        else             { CP_WAIT0(); }
        __syncthreads();

        const uint32_t st = sbase + (cc & 1) * STAGE_B;
#pragma unroll
        for (int s = 0; s < 8; s++) {
            const uint32_t ac = ac0 + 2 * s;
            const uint32_t bc = bc0 + 2 * s;

            uint32_t ah[4][4];
#pragma unroll
            for (int am = 0; am < 4; am++)
                ldsm4(ah[am], st + OFF_A + aRow[am] + ((ac ^ aX[am]) << 4));
            uint32_t bv[4][2];
#pragma unroll
            for (int pb = 0; pb < 2; pb++) {
                uint32_t r[4];
                ldsm4(r, st + OFF_W + bRow[pb] + ((bc ^ bX[pb]) << 4));
                bv[2 * pb][0] = r[0]; bv[2 * pb][1] = r[1];
                bv[2 * pb + 1][0] = r[2]; bv[2 * pb + 1][1] = r[3];
            }
#pragma unroll
            for (int am = 0; am < 4; am++)
#pragma unroll
                for (int an = 0; an < 4; an++) mma_f16(acc[am][an], ah[am], bv[an]);
        }
        __syncthreads();
    }

    // epilogue: bias (+ReLU), store fp32 or fp16
#pragma unroll
    for (int am = 0; am < 4; am++) {
        const int r0 = m0 + wm + am * 16 + (lane >> 2);
        const int r1 = r0 + 8;
#pragma unroll
        for (int an = 0; an < 4; an++) {
            const int col = n0 + wn + an * 8 + ((lane & 3) << 1);
            const float bz0 = __ldg(&bias[col]);
            const float bz1 = __ldg(&bias[col + 1]);
            float v00 = acc[am][an][0] + bz0;
            float v01 = acc[am][an][1] + bz1;
            float v10 = acc[am][an][2] + bz0;
            float v11 = acc[am][an][3] + bz1;
            if (ACT) {
                v00 = fmaxf(v00, 0.f); v01 = fmaxf(v01, 0.f);
                v10 = fmaxf(v10, 0.f); v11 = fmaxf(v11, 0.f);
            }
            if (OUT_HALF) {
                *reinterpret_cast<uint32_t*>(&Ch[(size_t)r0 * N + col]) = pack_h2(v00, v01);
                *reinterpret_cast<uint32_t*>(&Ch[(size_t)r1 * N + col]) = pack_h2(v10, v11);
            } else {
                *reinterpret_cast<float2*>(&C[(size_t)r0 * N + col]) = make_float2(v00, v01);
                *reinterpret_cast<float2*>(&C[(size_t)r1 * N + col]) = make_float2(v10, v11);
            }
        }
    }
}

// ---------------- fp32 -> fp16 converts (all weights, one launch) ----------
__device__ __forceinline__ void conv4(const float* src, __half* dst, int i) {
    float4 v = *reinterpret_cast<const float4*>(src + i);
    *reinterpret_cast<uint2*>(&dst[i]) =
        make_uint2(pack_h2(v.x, v.y), pack_h2(v.z, v.w));
}

__global__ __launch_bounds__(256) void conv_weights_kernel(
    const float* __restrict__ W1, __half* __restrict__ w1,
    const float* __restrict__ W2, __half* __restrict__ w2,
    const float* __restrict__ W3, __half* __restrict__ w3,
    const float* __restrict__ Wih, __half* __restrict__ wih,
    const float* __restrict__ Whh, __half* __restrict__ whh)
{
    const int N1 = H1_ * D_IN, N2 = H2_ * H1_, N3 = E_ * H2_;
    const int N4 = 4 * H_ * E_, N5 = 4 * H_ * H_;
    int i = (blockIdx.x * 256 + threadIdx.x) * 4;
    if (i < N1)                      conv4(W1, w1, i);
    else if (i < N1 + N2)            conv4(W2, w2, i - N1);
    else if (i < N1 + N2 + N3)       conv4(W3, w3, i - N1 - N2);
    else if (i < N1 + N2 + N3 + N4)  conv4(Wih, wih, i - N1 - N2 - N3);
    else if (i < N1 + N2 + N3 + N4 + N5) conv4(Whh, whh, i - N1 - N2 - N3 - N4);
}

// ============ fused shuffle: 5 x (online-softmax attention + LSTM) =========
// One block per batch, 1024 threads (32 warps). emb fp16; LSTM weights fp16.
// Attention streams 2 f-rows per step (two independent reduce chains).
__global__ __launch_bounds__(1024) void shuffle_kernel(
    const __half* __restrict__ emb, const int* __restrict__ length,
    const __half* __restrict__ W_ih, const __half* __restrict__ W_hh,
    const float* __restrict__ b_ih, const float* __restrict__ b_hh,
    float* __restrict__ out)
{
    const int b    = blockIdx.x;
    const int tid  = threadIdx.x;
    const int warp = tid >> 5, lane = tid & 31;

    __shared__ __align__(16) float s_q[H_];         // qt
    __shared__ __align__(16) float s_c[H_];         // ct
    __shared__ __align__(16) float s_x[E_];         // attended
    __shared__ __align__(16) float s_g[4 * H_];     // lstm gates
    __shared__ __align__(16) float s_part[32][E_ + 4];
    __shared__ float s_m[32], s_l[32], s_fac[32];
    __shared__ float s_invL;

    if (tid < H_) { s_q[tid] = 0.f; s_c[tid] = 0.f; }
    __syncthreads();

    const int len = length[b];
    const __half* eb = emb + (size_t)b * F_ * E_;
    const float4* q4 = reinterpret_cast<const float4*>(s_q);
    const float4* x4 = reinterpret_cast<const float4*>(s_x);

    for (int it = 0; it < NSH; it++) {
        // ---- single-pass attention: 2-row unrolled online softmax ----
        float m = -INFINITY, l = 0.f;
        float acc[8];
#pragma unroll
        for (int j = 0; j < 8; j++) acc[j] = 0.f;
        const float4 qa = q4[lane * 2], qb = q4[lane * 2 + 1];
        const float qv[8] = { qa.x, qa.y, qa.z, qa.w, qb.x, qb.y, qb.z, qb.w };
        const int fb = warp * 32;
#pragma unroll 2
        for (int ff = 0; ff < 32; ff += 2) {
            const int f0 = fb + ff, f1 = f0 + 1;
            const uint4 h0 = reinterpret_cast<const uint4*>(eb + (size_t)f0 * E_)[lane];
            const uint4 h1 = reinterpret_cast<const uint4*>(eb + (size_t)f1 * E_)[lane];
            const __half2* p0 = reinterpret_cast<const __half2*>(&h0);
            const __half2* p1 = reinterpret_cast<const __half2*>(&h1);
            float v0[8], v1[8];
#pragma unroll
            for (int k = 0; k < 4; k++) {
                const float2 a2 = __half22float2(p0[k]);
                const float2 b2 = __half22float2(p1[k]);
                v0[2 * k] = a2.x; v0[2 * k + 1] = a2.y;
                v1[2 * k] = b2.x; v1[2 * k + 1] = b2.y;
            }
            float d0 = v0[0] * qv[0], d1 = v1[0] * qv[0];
#pragma unroll
            for (int j = 1; j < 8; j++) {
                d0 = fmaf(v0[j], qv[j], d0);
                d1 = fmaf(v1[j], qv[j], d1);
            }
#pragma unroll
            for (int o = 16; o; o >>= 1) {
                d0 += __shfl_xor_sync(0xffffffffu, d0, o);
                d1 += __shfl_xor_sync(0xffffffffu, d1, o);
            }
            if (f0 < len) {
                const float mn = fmaxf(m, d0);
                const float sc = expf(m - mn);
                const float p  = expf(d0 - mn);
                l = l * sc + p;
#pragma unroll
                for (int j = 0; j < 8; j++) acc[j] = fmaf(acc[j], sc, p * v0[j]);
                m = mn;
            }
            if (f1 < len) {
                const float mn = fmaxf(m, d1);
                const float sc = expf(m - mn);
                const float p  = expf(d1 - mn);
                l = l * sc + p;
#pragma unroll
                for (int j = 0; j < 8; j++) acc[j] = fmaf(acc[j], sc, p * v1[j]);
                m = mn;
            }
        }
        {
            float4* sp = reinterpret_cast<float4*>(s_part[warp]);
            sp[lane * 2]     = make_float4(acc[0], acc[1], acc[2], acc[3]);
            sp[lane * 2 + 1] = make_float4(acc[4], acc[5], acc[6], acc[7]);
            if (lane == 0) { s_m[warp] = m; s_l[warp] = l; }
        }
        __syncthreads();

        // ---- combine 32 warp-partials (warp 0) ----
        if (tid < 32) {
            const float mw = s_m[tid];
            float M = mw;
#pragma unroll
            for (int o = 16; o; o >>= 1) M = fmaxf(M, __shfl_xor_sync(0xffffffffu, M, o));
            const float fac = expf(mw - M);
            s_fac[tid] = fac;
            float L = s_l[tid] * fac;
#pragma unroll
            for (int o = 16; o; o >>= 1) L += __shfl_xor_sync(0xffffffffu, L, o);
            if (tid == 0) s_invL = 1.f / L;
        }
        __syncthreads();

        if (tid < E_) {
            float s = 0.f;
#pragma unroll
            for (int w = 0; w < 32; w++) s = fmaf(s_part[w][tid], s_fac[w], s);
            s_x[tid] = s * s_invL;
        }
        __syncthreads();

        // ---- LSTM gates: warp per 32 rows, fp16 weights ----
        {
            const float4 xa = x4[lane * 2], xb = x4[lane * 2 + 1];
            const float xv[8] = { xa.x, xa.y, xa.z, xa.w, xb.x, xb.y, xb.z, xb.w };
            const float4 qa2 = q4[lane * 2], qb2 = q4[lane * 2 + 1];
            const float qw[8] = { qa2.x, qa2.y, qa2.z, qa2.w, qb2.x, qb2.y, qb2.z, qb2.w };
            for (int j = warp * 32, je = j + 32; j < je; j++) {
                const uint4 wiv = reinterpret_cast<const uint4*>(W_ih + (size_t)j * E_)[lane];
                const uint4 whv = reinterpret_cast<const uint4*>(W_hh + (size_t)j * H_)[lane];
                const __half2* wi2 = reinterpret_cast<const __half2*>(&wiv);
                const __half2* wh2 = reinterpret_cast<const __half2*>(&whv);
                float d = 0.f;
#pragma unroll
                for (int k = 0; k < 4; k++) {
                    const float2 wi = __half22float2(wi2[k]);
                    const float2 wh = __half22float2(wh2[k]);
                    d = fmaf(wi.x, xv[2 * k], d);
                    d = fmaf(wi.y, xv[2 * k + 1], d);
                    d = fmaf(wh.x, qw[2 * k], d);
                    d = fmaf(wh.y, qw[2 * k + 1], d);
                }
#pragma unroll
                for (int o = 16; o; o >>= 1) d += __shfl_xor_sync(0xffffffffu, d, o);
                if (lane == 0) s_g[j] = d + b_ih[j] + b_hh[j];
            }
        }
        __syncthreads();

        // ---- state update (gate order i, f, g, o) ----
        if (tid < H_) {
            const float gi = 1.f / (1.f + expf(-s_g[tid]));
            const float gf = 1.f / (1.f + expf(-s_g[H_ + tid]));
            const float gg = tanhf(s_g[2 * H_ + tid]);
            const float go = 1.f / (1.f + expf(-s_g[3 * H_ + tid]));
            const float c = gf * s_c[tid] + gi * gg;
            s_c[tid] = c;
            s_q[tid] = go * tanhf(c);
        }
        __syncthreads();
    }

    // ---- output: concat(attended, qt) ----
    if (tid < E_ + H_)
        out[b * (E_ + H_) + tid] = (tid < E_) ? s_x[tid] : s_q[tid - E_];
}

// ---------------- launch ----------------------------------------------------
extern "C" void kernel_launch(void* const* d_in, const int* in_sizes, int n_in,
                              void* d_out, int out_size)
{
    const float* state = (const float*)d_in[0];
    const int*   length= (const int*)  d_in[1];
    const float* W1    = (const float*)d_in[2];
    const float* b1    = (const float*)d_in[3];
    const float* W2    = (const float*)d_in[4];
    const float* b2    = (const float*)d_in[5];
    const float* W3    = (const float*)d_in[6];
    const float* b3    = (const float*)d_in[7];
    const float* W_ih  = (const float*)d_in[8];
    const float* W_hh  = (const float*)d_in[9];
    const float* b_ih  = (const float*)d_in[10];
    const float* b_hh  = (const float*)d_in[11];
    float* out = (float*)d_out;

    __half *h1, *h2, *w1, *w2, *w3, *wih, *whh, *embh;
    cudaGetSymbolAddress((void**)&h1,   g_h1);
    cudaGetSymbolAddress((void**)&h2,   g_h2);
    cudaGetSymbolAddress((void**)&w1,   g_w1);
    cudaGetSymbolAddress((void**)&w2,   g_w2);
    cudaGetSymbolAddress((void**)&w3,   g_w3);
    cudaGetSymbolAddress((void**)&wih,  g_wih);
    cudaGetSymbolAddress((void**)&whh,  g_whh);
    cudaGetSymbolAddress((void**)&embh, g_embh);

    cudaFuncSetAttribute(gemm_f16_kernel<1, 1, 1>,
                         cudaFuncAttributeMaxDynamicSharedMemorySize, GEMM_SM);
    cudaFuncSetAttribute(gemm_f16_kernel<1, 1, 0>,
                         cudaFuncAttributeMaxDynamicSharedMemorySize, GEMM_SM);
    cudaFuncSetAttribute(gemm_f16_kernel<0, 1, 0>,
                         cudaFuncAttributeMaxDynamicSharedMemorySize, GEMM_SM);

    // 1: all weight converts (embedder + LSTM), one launch
    {
        int n = H1_ * D_IN + H2_ * H1_ + E_ * H2_ + 4 * H_ * E_ + 4 * H_ * H_;
        conv_weights_kernel<<<n / 1024, 256>>>(W1, w1, W2, w2, W3, w3,
                                               W_ih, wih, W_hh, whh);
    }

    // 2-4: embedder MLP, single-pass fp16 HMMA (BK=128)
    {
        dim3 g1(H1_ / 256, MROWS / 128);
        gemm_f16_kernel<1, 1, 1><<<g1, 512, GEMM_SM>>>(
            MROWS, H1_, D_IN, nullptr, state, w1, b1, nullptr, h1);
        dim3 g2(H2_ / 256, MROWS / 128);
        gemm_f16_kernel<1, 1, 0><<<g2, 512, GEMM_SM>>>(
            MROWS, H2_, H1_, h1, nullptr, w2, b2, nullptr, h2);
        dim3 g3(E_ / 256, MROWS / 128);
        gemm_f16_kernel<0, 1, 0><<<g3, 512, GEMM_SM>>>(
            MROWS, E_, H2_, h2, nullptr, w3, b3, nullptr, embh);
    }

    // 5: fused shuffle loop (online-softmax attention + LSTM x5) + output
    shuffle_kernel<<<B_, 1024>>>(embh, length, wih, whh, b_ih, b_hh, out);
}

// round 13
// speedup vs baseline: 5.5794x; 1.0468x over previous
#include <cuda_runtime.h>
#include <cuda_fp16.h>
#include <math.h>
#include <stdint.h>

// Problem constants
#define B_    128
#define F_    1024
#define D_IN  128
#define H1_   512
#define H2_   512
#define E_    256
#define H_    256
#define NSH   5
#define MROWS (B_ * F_)   // 131072

// ---------------- scratch (device globals; no allocation allowed) ----------
__device__ __half g_h1[(size_t)MROWS * H1_];
__device__ __half g_h2[(size_t)MROWS * H2_];
__device__ __half g_w1[H1_ * D_IN];
__device__ __half g_w2[H2_ * H1_];
__device__ __half g_w3[E_ * H2_];
__device__ __half g_wih[4 * H_ * E_];
__device__ __half g_whh[4 * H_ * H_];
__device__ __half g_embh[(size_t)MROWS * E_];   // 67 MB, fp16 emb

// ===================== low-level helpers ===================================
__device__ __forceinline__ uint32_t smem_u32(const void* p) {
    uint32_t a;
    asm("{ .reg .u64 t; cvta.to.shared.u64 t, %1; cvt.u32.u64 %0, t; }"
        : "=r"(a) : "l"(p));
    return a;
}

__device__ __forceinline__ void cp_async16(uint32_t dst, const void* src) {
    asm volatile("cp.async.cg.shared.global [%0], [%1], 16;\n"
                 :: "r"(dst), "l"(src));
}
#define CP_COMMIT() asm volatile("cp.async.commit_group;\n" ::: "memory")
#define CP_WAIT1()  asm volatile("cp.async.wait_group 1;\n" ::: "memory")
#define CP_WAIT0()  asm volatile("cp.async.wait_group 0;\n" ::: "memory")

__device__ __forceinline__ void ldsm4(uint32_t* r, uint32_t addr) {
    asm volatile("ldmatrix.sync.aligned.m8n8.x4.shared.b16 {%0,%1,%2,%3}, [%4];\n"
                 : "=r"(r[0]), "=r"(r[1]), "=r"(r[2]), "=r"(r[3]) : "r"(addr));
}

// fp16 HMMA m16n8k16, fp32 accumulate
__device__ __forceinline__ void mma_f16(float* d, const uint32_t* a, const uint32_t* b) {
    asm volatile(
        "mma.sync.aligned.m16n8k16.row.col.f32.f16.f16.f32 "
        "{%0,%1,%2,%3}, {%4,%5,%6,%7}, {%8,%9}, {%0,%1,%2,%3};\n"
        : "+f"(d[0]), "+f"(d[1]), "+f"(d[2]), "+f"(d[3])
        : "r"(a[0]), "r"(a[1]), "r"(a[2]), "r"(a[3]), "r"(b[0]), "r"(b[1]));
}

__device__ __forceinline__ uint32_t pack_h2(float a, float b) {
    __half2 t = __floats2half2_rn(a, b);
    return reinterpret_cast<uint32_t&>(t);
}

// =================== fp16 HMMA GEMM: C = act(A @ W^T + bias) ================
// CTA tile 128x256, 256 threads, warp grid 2m x 4n, warp tile 64x64.
// 4 MMAs per LDSM (halved smem read traffic vs 64x32 warp tile).
// BK=128 (256B rows, XOR swizzle), 2-stage cp.async, 1 CTA/SM.
// CONV_A: A is fp32 in global; staged via LDG->cvt->STS (layer 1, K=128).
static constexpr int TA      = 128 * 256;          // 32768 B  A tile
static constexpr int TW      = 256 * 256;          // 65536 B  W tile
static constexpr int OFF_A   = 0;
static constexpr int OFF_W   = TA;
static constexpr int STAGE_B = TA + TW;            // 98304 B
static constexpr int GEMM_SM = 2 * STAGE_B;        // 196608 B

template <int ACT, int OUT_HALF, int CONV_A>
__global__ __launch_bounds__(256, 1) void gemm_f16_kernel(
    int M, int N, int K,
    const __half* __restrict__ A, const float* __restrict__ Afp,
    const __half* __restrict__ W,
    const float* __restrict__ bias,
    float* __restrict__ C, __half* __restrict__ Ch)
{
    extern __shared__ char smem[];
    const uint32_t sbase = smem_u32(smem);
    const int tid  = threadIdx.x;
    const int lane = tid & 31;
    const int wid  = tid >> 5;            // 0..7
    const int m0 = blockIdx.y * 128;
    const int n0 = blockIdx.x * 256;
    const int wm = (wid & 1) * 64;        // warp m-offset
    const int wn = (wid >> 1) * 64;       // warp n-offset (0..192)

    float acc[4][8][4];
#pragma unroll
    for (int i = 0; i < 4; i++)
#pragma unroll
        for (int j = 0; j < 8; j++)
#pragma unroll
            for (int k = 0; k < 4; k++) acc[i][j][k] = 0.f;

    // ---- ldmatrix row bases ----
    uint32_t aRow[4], aX[4];
#pragma unroll
    for (int am = 0; am < 4; am++) {
        const int r = wm + am * 16 + (lane & 15);
        aRow[am] = (uint32_t)(r * 256);
        aX[am]   = (uint32_t)(r & 7);
    }
    uint32_t bRow[4], bX[4];
#pragma unroll
    for (int pb = 0; pb < 4; pb++) {
        const int r = wn + pb * 16 + (lane & 7) + ((lane >> 1) & 8);
        bRow[pb] = (uint32_t)(r * 256);
        bX[pb]   = (uint32_t)(r & 7);
    }
    const uint32_t ac0 = (uint32_t)(lane >> 4);
    const uint32_t bc0 = (uint32_t)((lane >> 3) & 1);

    const int NC = K >> 7;   // chunks of 128 fp16

    // staging: 16 W-chunks + 8 A-chunks of 16B per thread per stage
    auto prefetch = [&](int cc, int st) {
        const uint32_t so = sbase + (uint32_t)(st * STAGE_B);
        const int kk = cc * 128;
#pragma unroll
        for (int i = 0; i < 16; i++) {
            const int id  = i * 256 + tid;       // 0..4095
            const int row = id >> 4;
            const int c16 = id & 15;
            cp_async16(so + OFF_W + row * 256 + (((uint32_t)(c16 ^ (row & 7))) << 4),
                       W + (size_t)(n0 + row) * K + kk + c16 * 8);
        }
        if (CONV_A) {
#pragma unroll
            for (int i = 0; i < 8; i++) {
                const int id  = i * 256 + tid;   // 0..2047
                const int row = id >> 4;
                const int c16 = id & 15;
                const float* src = Afp + (size_t)(m0 + row) * K + kk + c16 * 8;
                const float4 u = *reinterpret_cast<const float4*>(src);
                const float4 v = *reinterpret_cast<const float4*>(src + 4);
                uint4 pk;
                pk.x = pack_h2(u.x, u.y); pk.y = pack_h2(u.z, u.w);
                pk.z = pack_h2(v.x, v.y); pk.w = pack_h2(v.z, v.w);
                *reinterpret_cast<uint4*>(
                    smem + (so - sbase) + OFF_A + row * 256
                    + (((uint32_t)(c16 ^ (row & 7))) << 4)) = pk;
            }
        } else {
#pragma unroll
            for (int i = 0; i < 8; i++) {
                const int id  = i * 256 + tid;
                const int row = id >> 4;
                const int c16 = id & 15;
                cp_async16(so + OFF_A + row * 256 + (((uint32_t)(c16 ^ (row & 7))) << 4),
                           A + (size_t)(m0 + row) * K + kk + c16 * 8);
            }
        }
        CP_COMMIT();
    };

    prefetch(0, 0);

    for (int cc = 0; cc < NC; cc++) {
        if (cc + 1 < NC) { prefetch(cc + 1, (cc + 1) & 1); CP_WAIT1(); }
        else             { CP_WAIT0(); }
        __syncthreads();

        const uint32_t st = sbase + (cc & 1) * STAGE_B;
#pragma unroll
        for (int s = 0; s < 8; s++) {
            const uint32_t ac = ac0 + 2 * s;
            const uint32_t bc = bc0 + 2 * s;

            uint32_t ah[4][4];
#pragma unroll
            for (int am = 0; am < 4; am++)
                ldsm4(ah[am], st + OFF_A + aRow[am] + ((ac ^ aX[am]) << 4));
            uint32_t bv[8][2];
#pragma unroll
            for (int pb = 0; pb < 4; pb++) {
                uint32_t r[4];
                ldsm4(r, st + OFF_W + bRow[pb] + ((bc ^ bX[pb]) << 4));
                bv[2 * pb][0] = r[0]; bv[2 * pb][1] = r[1];
                bv[2 * pb + 1][0] = r[2]; bv[2 * pb + 1][1] = r[3];
            }
#pragma unroll
            for (int am = 0; am < 4; am++)
#pragma unroll
                for (int an = 0; an < 8; an++) mma_f16(acc[am][an], ah[am], bv[an]);
        }
        __syncthreads();
    }

    // epilogue: bias (+ReLU), store fp32 or fp16
#pragma unroll
    for (int am = 0; am < 4; am++) {
        const int r0 = m0 + wm + am * 16 + (lane >> 2);
        const int r1 = r0 + 8;
#pragma unroll
        for (int an = 0; an < 8; an++) {
            const int col = n0 + wn + an * 8 + ((lane & 3) << 1);
            const float bz0 = __ldg(&bias[col]);
            const float bz1 = __ldg(&bias[col + 1]);
            float v00 = acc[am][an][0] + bz0;
            float v01 = acc[am][an][1] + bz1;
            float v10 = acc[am][an][2] + bz0;
            float v11 = acc[am][an][3] + bz1;
            if (ACT) {
                v00 = fmaxf(v00, 0.f); v01 = fmaxf(v01, 0.f);
                v10 = fmaxf(v10, 0.f); v11 = fmaxf(v11, 0.f);
            }
            if (OUT_HALF) {
                *reinterpret_cast<uint32_t*>(&Ch[(size_t)r0 * N + col]) = pack_h2(v00, v01);
                *reinterpret_cast<uint32_t*>(&Ch[(size_t)r1 * N + col]) = pack_h2(v10, v11);
            } else {
                *reinterpret_cast<float2*>(&C[(size_t)r0 * N + col]) = make_float2(v00, v01);
                *reinterpret_cast<float2*>(&C[(size_t)r1 * N + col]) = make_float2(v10, v11);
            }
        }
    }
}

// ---------------- fp32 -> fp16 converts (all weights, one launch) ----------
__device__ __forceinline__ void conv4(const float* src, __half* dst, int i) {
    float4 v = *reinterpret_cast<const float4*>(src + i);
    *reinterpret_cast<uint2*>(&dst[i]) =
        make_uint2(pack_h2(v.x, v.y), pack_h2(v.z, v.w));
}

__global__ __launch_bounds__(256) void conv_weights_kernel(
    const float* __restrict__ W1, __half* __restrict__ w1,
    const float* __restrict__ W2, __half* __restrict__ w2,
    const float* __restrict__ W3, __half* __restrict__ w3,
    const float* __restrict__ Wih, __half* __restrict__ wih,
    const float* __restrict__ Whh, __half* __restrict__ whh)
{
    const int N1 = H1_ * D_IN, N2 = H2_ * H1_, N3 = E_ * H2_;
    const int N4 = 4 * H_ * E_, N5 = 4 * H_ * H_;
    int i = (blockIdx.x * 256 + threadIdx.x) * 4;
    if (i < N1)                      conv4(W1, w1, i);
    else if (i < N1 + N2)            conv4(W2, w2, i - N1);
    else if (i < N1 + N2 + N3)       conv4(W3, w3, i - N1 - N2);
    else if (i < N1 + N2 + N3 + N4)  conv4(Wih, wih, i - N1 - N2 - N3);
    else if (i < N1 + N2 + N3 + N4 + N5) conv4(Whh, whh, i - N1 - N2 - N3 - N4);
}

// ============ fused shuffle: 5 x (online-softmax attention + LSTM) =========
// One block per batch, 1024 threads (32 warps). emb fp16; LSTM weights fp16.
__global__ __launch_bounds__(1024) void shuffle_kernel(
    const __half* __restrict__ emb, const int* __restrict__ length,
    const __half* __restrict__ W_ih, const __half* __restrict__ W_hh,
    const float* __restrict__ b_ih, const float* __restrict__ b_hh,
    float* __restrict__ out)
{
    const int b    = blockIdx.x;
    const int tid  = threadIdx.x;
    const int warp = tid >> 5, lane = tid & 31;

    __shared__ __align__(16) float s_q[H_];         // qt
    __shared__ __align__(16) float s_c[H_];         // ct
    __shared__ __align__(16) float s_x[E_];         // attended
    __shared__ __align__(16) float s_g[4 * H_];     // lstm gates
    __shared__ __align__(16) float s_part[32][E_ + 4];
    __shared__ float s_m[32], s_l[32], s_fac[32];
    __shared__ float s_invL;

    if (tid < H_) { s_q[tid] = 0.f; s_c[tid] = 0.f; }
    __syncthreads();

    const int len = length[b];
    const __half* eb = emb + (size_t)b * F_ * E_;
    const float4* q4 = reinterpret_cast<const float4*>(s_q);
    const float4* x4 = reinterpret_cast<const float4*>(s_x);

    for (int it = 0; it < NSH; it++) {
        // ---- single-pass attention: 2-row unrolled online softmax ----
        float m = -INFINITY, l = 0.f;
        float acc[8];
#pragma unroll
        for (int j = 0; j < 8; j++) acc[j] = 0.f;
        const float4 qa = q4[lane * 2], qb = q4[lane * 2 + 1];
        const float qv[8] = { qa.x, qa.y, qa.z, qa.w, qb.x, qb.y, qb.z, qb.w };
        const int fb = warp * 32;
#pragma unroll 2
        for (int ff = 0; ff < 32; ff += 2) {
            const int f0 = fb + ff, f1 = f0 + 1;
            const uint4 h0 = reinterpret_cast<const uint4*>(eb + (size_t)f0 * E_)[lane];
            const uint4 h1 = reinterpret_cast<const uint4*>(eb + (size_t)f1 * E_)[lane];
            const __half2* p0 = reinterpret_cast<const __half2*>(&h0);
            const __half2* p1 = reinterpret_cast<const __half2*>(&h1);
            float v0[8], v1[8];
#pragma unroll
            for (int k = 0; k < 4; k++) {
                const float2 a2 = __half22float2(p0[k]);
                const float2 b2 = __half22float2(p1[k]);
                v0[2 * k] = a2.x; v0[2 * k + 1] = a2.y;
                v1[2 * k] = b2.x; v1[2 * k + 1] = b2.y;
            }
            float d0 = v0[0] * qv[0], d1 = v1[0] * qv[0];
#pragma unroll
            for (int j = 1; j < 8; j++) {
                d0 = fmaf(v0[j], qv[j], d0);
                d1 = fmaf(v1[j], qv[j], d1);
            }
#pragma unroll
            for (int o = 16; o; o >>= 1) {
                d0 += __shfl_xor_sync(0xffffffffu, d0, o);
                d1 += __shfl_xor_sync(0xffffffffu, d1, o);
            }
            if (f0 < len) {
                const float mn = fmaxf(m, d0);
                const float sc = expf(m - mn);
                const float p  = expf(d0 - mn);
                l = l * sc + p;
#pragma unroll
                for (int j = 0; j < 8; j++) acc[j] = fmaf(acc[j], sc, p * v0[j]);
                m = mn;
            }
            if (f1 < len) {
                const float mn = fmaxf(m, d1);
                const float sc = expf(m - mn);
                const float p  = expf(d1 - mn);
                l = l * sc + p;
#pragma unroll
                for (int j = 0; j < 8; j++) acc[j] = fmaf(acc[j], sc, p * v1[j]);
                m = mn;
            }
        }
        {
            float4* sp = reinterpret_cast<float4*>(s_part[warp]);
            sp[lane * 2]     = make_float4(acc[0], acc[1], acc[2], acc[3]);
            sp[lane * 2 + 1] = make_float4(acc[4], acc[5], acc[6], acc[7]);
            if (lane == 0) { s_m[warp] = m; s_l[warp] = l; }
        }
        __syncthreads();

        // ---- combine 32 warp-partials (warp 0) ----
        if (tid < 32) {
            const float mw = s_m[tid];
            float M = mw;
#pragma unroll
            for (int o = 16; o; o >>= 1) M = fmaxf(M, __shfl_xor_sync(0xffffffffu, M, o));
            const float fac = expf(mw - M);
            s_fac[tid] = fac;
            float L = s_l[tid] * fac;
#pragma unroll
            for (int o = 16; o; o >>= 1) L += __shfl_xor_sync(0xffffffffu, L, o);
            if (tid == 0) s_invL = 1.f / L;
        }
        __syncthreads();

        if (tid < E_) {
            float s = 0.f;
#pragma unroll
            for (int w = 0; w < 32; w++) s = fmaf(s_part[w][tid], s_fac[w], s);
            s_x[tid] = s * s_invL;
        }
        __syncthreads();

        // ---- LSTM gates: warp per 32 rows, fp16 weights ----
        {
            const float4 xa = x4[lane * 2], xb = x4[lane * 2 + 1];
            const float xv[8] = { xa.x, xa.y, xa.z, xa.w, xb.x, xb.y, xb.z, xb.w };
            const float4 qa2 = q4[lane * 2], qb2 = q4[lane * 2 + 1];
            const float qw[8] = { qa2.x, qa2.y, qa2.z, qa2.w, qb2.x, qb2.y, qb2.z, qb2.w };
            for (int j = warp * 32, je = j + 32; j < je; j++) {
                const uint4 wiv = reinterpret_cast<const uint4*>(W_ih + (size_t)j * E_)[lane];
                const uint4 whv = reinterpret_cast<const uint4*>(W_hh + (size_t)j * H_)[lane];
                const __half2* wi2 = reinterpret_cast<const __half2*>(&wiv);
                const __half2* wh2 = reinterpret_cast<const __half2*>(&whv);
                float d = 0.f;
#pragma unroll
                for (int k = 0; k < 4; k++) {
                    const float2 wi = __half22float2(wi2[k]);
                    const float2 wh = __half22float2(wh2[k]);
                    d = fmaf(wi.x, xv[2 * k], d);
                    d = fmaf(wi.y, xv[2 * k + 1], d);
                    d = fmaf(wh.x, qw[2 * k], d);
                    d = fmaf(wh.y, qw[2 * k + 1], d);
                }
#pragma unroll
                for (int o = 16; o; o >>= 1) d += __shfl_xor_sync(0xffffffffu, d, o);
                if (lane == 0) s_g[j] = d + b_ih[j] + b_hh[j];
            }
        }
        __syncthreads();

        // ---- state update (gate order i, f, g, o) ----
        if (tid < H_) {
            const float gi = 1.f / (1.f + expf(-s_g[tid]));
            const float gf = 1.f / (1.f + expf(-s_g[H_ + tid]));
            const float gg = tanhf(s_g[2 * H_ + tid]);
            const float go = 1.f / (1.f + expf(-s_g[3 * H_ + tid]));
            const float c = gf * s_c[tid] + gi * gg;
            s_c[tid] = c;
            s_q[tid] = go * tanhf(c);
        }
        __syncthreads();
    }

    // ---- output: concat(attended, qt) ----
    if (tid < E_ + H_)
        out[b * (E_ + H_) + tid] = (tid < E_) ? s_x[tid] : s_q[tid - E_];
}

// ---------------- launch ----------------------------------------------------
extern "C" void kernel_launch(void* const* d_in, const int* in_sizes, int n_in,
                              void* d_out, int out_size)
{
    const float* state = (const float*)d_in[0];
    const int*   length= (const int*)  d_in[1];
    const float* W1    = (const float*)d_in[2];
    const float* b1    = (const float*)d_in[3];
    const float* W2    = (const float*)d_in[4];
    const float* b2    = (const float*)d_in[5];
    const float* W3    = (const float*)d_in[6];
    const float* b3    = (const float*)d_in[7];
    const float* W_ih  = (const float*)d_in[8];
    const float* W_hh  = (const float*)d_in[9];
    const float* b_ih  = (const float*)d_in[10];
    const float* b_hh  = (const float*)d_in[11];
    float* out = (float*)d_out;

    __half *h1, *h2, *w1, *w2, *w3, *wih, *whh, *embh;
    cudaGetSymbolAddress((void**)&h1,   g_h1);
    cudaGetSymbolAddress((void**)&h2,   g_h2);
    cudaGetSymbolAddress((void**)&w1,   g_w1);
    cudaGetSymbolAddress((void**)&w2,   g_w2);
    cudaGetSymbolAddress((void**)&w3,   g_w3);
    cudaGetSymbolAddress((void**)&wih,  g_wih);
    cudaGetSymbolAddress((void**)&whh,  g_whh);
    cudaGetSymbolAddress((void**)&embh, g_embh);

    cudaFuncSetAttribute(gemm_f16_kernel<1, 1, 1>,
                         cudaFuncAttributeMaxDynamicSharedMemorySize, GEMM_SM);
    cudaFuncSetAttribute(gemm_f16_kernel<1, 1, 0>,
                         cudaFuncAttributeMaxDynamicSharedMemorySize, GEMM_SM);
    cudaFuncSetAttribute(gemm_f16_kernel<0, 1, 0>,
                         cudaFuncAttributeMaxDynamicSharedMemorySize, GEMM_SM);

    // 1: all weight converts (embedder + LSTM), one launch
    {
        int n = H1_ * D_IN + H2_ * H1_ + E_ * H2_ + 4 * H_ * E_ + 4 * H_ * H_;
        conv_weights_kernel<<<n / 1024, 256>>>(W1, w1, W2, w2, W3, w3,
                                               W_ih, wih, W_hh, whh);
    }

    // 2-4: embedder MLP, single-pass fp16 HMMA (BK=128, warp tile 64x64)
    {
        dim3 g1(H1_ / 256, MROWS / 128);
        gemm_f16_kernel<1, 1, 1><<<g1, 256, GEMM_SM>>>(
            MROWS, H1_, D_IN, nullptr, state, w1, b1, nullptr, h1);
        dim3 g2(H2_ / 256, MROWS / 128);
        gemm_f16_kernel<1, 1, 0><<<g2, 256, GEMM_SM>>>(
            MROWS, H2_, H1_, h1, nullptr, w2, b2, nullptr, h2);
        dim3 g3(E_ / 256, MROWS / 128);
        gemm_f16_kernel<0, 1, 0><<<g3, 256, GEMM_SM>>>(
            MROWS, E_, H2_, h2, nullptr, w3, b3, nullptr, embh);
    }

    // 5: fused shuffle loop (online-softmax attention + LSTM x5) + output
    shuffle_kernel<<<B_, 1024>>>(embh, length, wih, whh, b_ih, b_hh, out);
}